// round 1
// baseline (speedup 1.0000x reference)
#include <cuda_runtime.h>
#include <math.h>

#define SEQ 2048
#define NB  16
#define DM  1024
#define DH  512

static constexpr size_t ROWS = (size_t)SEQ * NB;   // 32768

// ---- scratch (device globals; no allocation allowed) ----
__device__ float g_q[ROWS * DH];                    //  64 MB  q = x@W1
__device__ float g_kv[ROWS * 2 * DH];               // 128 MB  kv = q@W2 (k | va)
__device__ float g_scores[(size_t)NB * SEQ * SEQ];  // 256 MB  attention scores/probs
__device__ float g_cq[ROWS * DH];                   //  64 MB  ctx + q
__device__ float g_U[ROWS * 3 * DM];                // 384 MB  U = (ctx+q)@W3

// ============================================================================
// Generic tiled SGEMM: C[M,N] = alpha * A @ op(B) (+ Ad), batched over grid.z.
// Tile 128x64x16, 256 threads, 8x4 per-thread microtile.
// TB=false: B is [K,N] row-major. TB=true: B is [N,K] row-major (C = A @ B^T).
// All M,N,K multiples of tile dims (shapes here are static & divisible).
// ============================================================================
template<bool TB, bool ADD>
__global__ __launch_bounds__(256)
void sgemm_k(const float* __restrict__ A, const float* __restrict__ B,
             float* __restrict__ C, const float* __restrict__ Ad,
             int K, int lda, int ldb, int ldc, int ldad, float alpha,
             long long sA, long long sB, long long sC, long long sAd)
{
    A += (long long)blockIdx.z * sA;
    B += (long long)blockIdx.z * sB;
    C += (long long)blockIdx.z * sC;
    if (ADD) Ad += (long long)blockIdx.z * sAd;

    const int m0 = blockIdx.y * 128;
    const int n0 = blockIdx.x * 64;
    const int tid = threadIdx.x;

    __shared__ float As[16][128];
    __shared__ float Bs[16][64];

    float acc[8][4];
    #pragma unroll
    for (int i = 0; i < 8; i++)
        #pragma unroll
        for (int j = 0; j < 4; j++) acc[i][j] = 0.f;

    const int tm = (tid >> 4) * 8;
    const int tn = (tid & 15) * 4;

    for (int k0 = 0; k0 < K; k0 += 16) {
        // load A tile (128 x 16), 8 elems/thread
        #pragma unroll
        for (int i = 0; i < 8; i++) {
            int idx = i * 256 + tid;
            int m = idx >> 4, k = idx & 15;
            As[k][m] = A[(long long)(m0 + m) * lda + k0 + k];
        }
        // load B tile (16 x 64), 4 elems/thread
        if (TB) {
            #pragma unroll
            for (int i = 0; i < 4; i++) {
                int idx = i * 256 + tid;
                int n = idx >> 4, k = idx & 15;
                Bs[k][n] = B[(long long)(n0 + n) * ldb + k0 + k];
            }
        } else {
            #pragma unroll
            for (int i = 0; i < 4; i++) {
                int idx = i * 256 + tid;
                int k = idx >> 6, n = idx & 63;
                Bs[k][n] = B[(long long)(k0 + k) * ldb + n0 + n];
            }
        }
        __syncthreads();

        #pragma unroll
        for (int kk = 0; kk < 16; kk++) {
            float4 b4 = *(const float4*)&Bs[kk][tn];
            float4 a0 = *(const float4*)&As[kk][tm];
            float4 a1 = *(const float4*)&As[kk][tm + 4];
            float av[8] = {a0.x, a0.y, a0.z, a0.w, a1.x, a1.y, a1.z, a1.w};
            float bv[4] = {b4.x, b4.y, b4.z, b4.w};
            #pragma unroll
            for (int i = 0; i < 8; i++)
                #pragma unroll
                for (int j = 0; j < 4; j++)
                    acc[i][j] = fmaf(av[i], bv[j], acc[i][j]);
        }
        __syncthreads();
    }

    #pragma unroll
    for (int i = 0; i < 8; i++) {
        int m = m0 + tm + i;
        #pragma unroll
        for (int j = 0; j < 4; j++) {
            int n = n0 + tn + j;
            float val = alpha * acc[i][j];
            if (ADD) val += Ad[(long long)m * ldad + n];
            C[(long long)m * ldc + n] = val;
        }
    }
}

// ============================================================================
// Row softmax over 2048-wide rows. One 256-thread block per row.
// ============================================================================
__global__ __launch_bounds__(256)
void softmax2048(float* __restrict__ S)
{
    float* row = S + (size_t)blockIdx.x * SEQ;
    const int tid = threadIdx.x;

    float vals[8];
    float m = -1e30f;
    #pragma unroll
    for (int i = 0; i < 8; i++) {
        vals[i] = row[tid + i * 256];
        m = fmaxf(m, vals[i]);
    }

    __shared__ float rmax[8];
    __shared__ float rsum[8];

    #pragma unroll
    for (int o = 16; o; o >>= 1) m = fmaxf(m, __shfl_xor_sync(0xffffffffu, m, o));
    if ((tid & 31) == 0) rmax[tid >> 5] = m;
    __syncthreads();
    m = rmax[0];
    #pragma unroll
    for (int w = 1; w < 8; w++) m = fmaxf(m, rmax[w]);

    float s = 0.f;
    #pragma unroll
    for (int i = 0; i < 8; i++) {
        vals[i] = __expf(vals[i] - m);
        s += vals[i];
    }
    #pragma unroll
    for (int o = 16; o; o >>= 1) s += __shfl_xor_sync(0xffffffffu, s, o);
    if ((tid & 31) == 0) rsum[tid >> 5] = s;
    __syncthreads();
    s = rsum[0];
    #pragma unroll
    for (int w = 1; w < 8; w++) s += rsum[w];

    float inv = 1.f / s;
    #pragma unroll
    for (int i = 0; i < 8; i++) row[tid + i * 256] = vals[i] * inv;
}

// ============================================================================
// Highway recurrence: each thread owns one (b, d) channel across all L steps.
// 16384 threads total, fully coalesced per step (consecutive d).
// ============================================================================
__global__ __launch_bounds__(256)
void sru_recur(const float* __restrict__ U, const float* __restrict__ x,
               const float* __restrict__ v, const float* __restrict__ bias,
               float* __restrict__ h)
{
    int t = blockIdx.x * 256 + threadIdx.x;   // 0 .. NB*DM-1
    int b = t / DM;
    int d = t % DM;

    float vf = v[d],       vr = v[DM + d];
    float bf = bias[d],    br = bias[DM + d];
    float c = 0.f;

    for (int l = 0; l < SEQ; l++) {
        long long r3 = ((long long)l * NB + b) * (3 * DM) + d;
        long long r1 = ((long long)l * NB + b) * DM + d;
        float xt   = U[r3];
        float fr   = U[r3 + DM];
        float rr   = U[r3 + 2 * DM];
        float xres = x[r1];

        float f = 1.f / (1.f + __expf(-(fr + vf * c + bf)));
        float r = 1.f / (1.f + __expf(-(rr + vr * c + br)));
        c = f * c + (1.f - f) * xt;
        h[r1] = r * c + (1.f - r) * xres;
    }
}

// ============================================================================
// Launch
// ============================================================================
extern "C" void kernel_launch(void* const* d_in, const int* in_sizes, int n_in,
                              void* d_out, int out_size)
{
    const float* x  = (const float*)d_in[0];   // [L,B,1024]
    const float* W1 = (const float*)d_in[1];   // [1024,512]
    const float* W2 = (const float*)d_in[2];   // [512,1024]
    const float* W3 = (const float*)d_in[3];   // [512,3072]
    const float* v  = (const float*)d_in[4];   // [2,1024]
    const float* bb = (const float*)d_in[5];   // [2,1024]
    float* h = (float*)d_out;                  // [L,B,1024]

    float *q, *kv, *sc, *cq, *U;
    cudaGetSymbolAddress((void**)&q,  g_q);
    cudaGetSymbolAddress((void**)&kv, g_kv);
    cudaGetSymbolAddress((void**)&sc, g_scores);
    cudaGetSymbolAddress((void**)&cq, g_cq);
    cudaGetSymbolAddress((void**)&U,  g_U);

    const dim3 T(256);
    const float scale = 1.0f / sqrtf((float)DH);

    // q = x @ W1 : [32768,1024] x [1024,512]
    sgemm_k<false, false><<<dim3(DH / 64, ROWS / 128, 1), T>>>(
        x, W1, q, nullptr, DM, DM, DH, DH, 0, 1.f, 0, 0, 0, 0);

    // kv = q @ W2 : [32768,512] x [512,1024]
    sgemm_k<false, false><<<dim3(2 * DH / 64, ROWS / 128, 1), T>>>(
        q, W2, kv, nullptr, DH, DH, 2 * DH, 2 * DH, 0, 1.f, 0, 0, 0, 0);

    // scores[b] = scale * Q_b @ K_b^T : per-batch [2048,512] x [2048,512]^T
    // Q_b rows stride NB*DH (layout [L,B,p]); K_b rows stride NB*2*DH in kv.
    sgemm_k<true, false><<<dim3(SEQ / 64, SEQ / 128, NB), T>>>(
        q, kv, sc, nullptr, DH, NB * DH, NB * 2 * DH, SEQ, 0, scale,
        (long long)DH, (long long)(2 * DH), (long long)SEQ * SEQ, 0);

    // softmax over last axis (rows of 2048)
    softmax2048<<<NB * SEQ, 256>>>(sc);

    // cq[b] = attn_b @ Va_b + Q_b : per-batch [2048,2048] x [2048,512]
    sgemm_k<false, true><<<dim3(DH / 64, SEQ / 128, NB), T>>>(
        sc, kv + DH, cq, q, SEQ, SEQ, NB * 2 * DH, NB * DH, NB * DH, 1.f,
        (long long)SEQ * SEQ, (long long)(2 * DH), (long long)DH, (long long)DH);

    // U = cq @ W3 : [32768,512] x [512,3072]
    sgemm_k<false, false><<<dim3(3 * DM / 64, ROWS / 128, 1), T>>>(
        cq, W3, U, nullptr, DH, DH, 3 * DM, 3 * DM, 0, 1.f, 0, 0, 0, 0);

    // elementwise highway recurrence over time
    sru_recur<<<(NB * DM) / 256, 256>>>(U, x, v, bb, h);
}

// round 2
// speedup vs baseline: 3.0934x; 3.0934x over previous
#include <cuda_runtime.h>
#include <math.h>
#include <stdint.h>

#define SEQ 2048
#define NB  16
#define DM  1024
#define DH  512

static constexpr size_t ROWS = (size_t)SEQ * NB;   // 32768

// ---- scratch (device globals; no allocation allowed) ----
__device__ float g_q[ROWS * DH];                    //  64 MB
__device__ float g_kv[ROWS * 2 * DH];               // 128 MB
__device__ float g_scores[(size_t)NB * SEQ * SEQ];  // 256 MB
__device__ float g_cq[ROWS * DH];                   //  64 MB
__device__ float g_U[ROWS * 3 * DM];                // 384 MB

__device__ __forceinline__ uint32_t f2tf32(float f) {
    uint32_t u;
    asm("cvt.rna.tf32.f32 %0, %1;" : "=r"(u) : "f"(f));
    return u;
}

__device__ __forceinline__ void mma_tf32(float* c, const uint32_t* a, const uint32_t* b) {
    asm volatile(
        "mma.sync.aligned.m16n8k8.row.col.f32.tf32.tf32.f32 "
        "{%0,%1,%2,%3}, {%4,%5,%6,%7}, {%8,%9}, {%0,%1,%2,%3};"
        : "+f"(c[0]), "+f"(c[1]), "+f"(c[2]), "+f"(c[3])
        : "r"(a[0]), "r"(a[1]), "r"(a[2]), "r"(a[3]), "r"(b[0]), "r"(b[1]));
}

// ============================================================================
// TF32 tensor-core GEMM: C[M,N] = alpha * A @ op(B) (+ Ad), batched over grid.z
// Block tile 128x128x16, 256 threads, warp grid 2(M)x4(N), warp tile 64x32.
// TB=false: B is [K,N] row-major.  TB=true: B is [N,K] row-major (C = A@B^T).
// All dims divide tiles exactly (static shapes).
// ============================================================================
#define PS 136   // padded SMEM row stride (floats): bank shift 8 per k-row

template<bool TB, bool ADD>
__global__ __launch_bounds__(256)
void mma_gemm(const float* __restrict__ A, const float* __restrict__ B,
              float* __restrict__ C, const float* __restrict__ Ad,
              int K, int lda, int ldb, int ldc, int ldad, float alpha,
              long long sA, long long sB, long long sC, long long sAd)
{
    A += (long long)blockIdx.z * sA;
    B += (long long)blockIdx.z * sB;
    C += (long long)blockIdx.z * sC;
    if (ADD) Ad += (long long)blockIdx.z * sAd;

    const int m0 = blockIdx.y * 128;
    const int n0 = blockIdx.x * 128;
    const int tid  = threadIdx.x;
    const int lane = tid & 31;
    const int warp = tid >> 5;
    const int wm = (warp >> 2) * 64;   // warp M offset (2 warps in M)
    const int wn = (warp & 3) * 32;    // warp N offset (4 warps in N)
    const int g = lane >> 2;           // group id (0..7)
    const int t = lane & 3;            // thread-in-group (0..3)

    __shared__ uint32_t As[2][16 * PS];
    __shared__ uint32_t Bs[2][16 * PS];

    float acc[4][4][4];
    #pragma unroll
    for (int mt = 0; mt < 4; mt++)
        #pragma unroll
        for (int nt = 0; nt < 4; nt++)
            #pragma unroll
            for (int r = 0; r < 4; r++) acc[mt][nt][r] = 0.f;

    // GMEM staging registers
    float4 ra[2], rb[2];

    const int am = tid >> 2;   // A row 0..63 (+64 for i=1)
    const int av = tid & 3;    // A float4 index within 16-wide row

    auto gload = [&](int k0) {
        #pragma unroll
        for (int i = 0; i < 2; i++) {
            ra[i] = *(const float4*)(A + (long long)(m0 + am + i * 64) * lda + k0 + av * 4);
            if (TB)
                rb[i] = *(const float4*)(B + (long long)(n0 + (tid >> 2) + i * 64) * ldb + k0 + (tid & 3) * 4);
            else
                rb[i] = *(const float4*)(B + (long long)(k0 + (tid >> 5) + i * 8) * ldb + n0 + (tid & 31) * 4);
        }
    };

    auto sstore = [&](int buf) {
        #pragma unroll
        for (int i = 0; i < 2; i++) {
            const float* fa = (const float*)&ra[i];
            #pragma unroll
            for (int j = 0; j < 4; j++)
                As[buf][(av * 4 + j) * PS + am + i * 64] = f2tf32(fa[j]);
            const float* fb = (const float*)&rb[i];
            if (TB) {
                #pragma unroll
                for (int j = 0; j < 4; j++)
                    Bs[buf][((tid & 3) * 4 + j) * PS + (tid >> 2) + i * 64] = f2tf32(fb[j]);
            } else {
                #pragma unroll
                for (int j = 0; j < 4; j++)
                    Bs[buf][((tid >> 5) + i * 8) * PS + (tid & 31) * 4 + j] = f2tf32(fb[j]);
            }
        }
    };

    auto compute = [&](int buf) {
        #pragma unroll
        for (int s = 0; s < 16; s += 8) {
            uint32_t af[4][4], bf[4][2];
            #pragma unroll
            for (int mt = 0; mt < 4; mt++) {
                int m = wm + mt * 16 + g;
                af[mt][0] = As[buf][(s + t) * PS + m];
                af[mt][1] = As[buf][(s + t) * PS + m + 8];
                af[mt][2] = As[buf][(s + t + 4) * PS + m];
                af[mt][3] = As[buf][(s + t + 4) * PS + m + 8];
            }
            #pragma unroll
            for (int nt = 0; nt < 4; nt++) {
                int n = wn + nt * 8 + g;
                bf[nt][0] = Bs[buf][(s + t) * PS + n];
                bf[nt][1] = Bs[buf][(s + t + 4) * PS + n];
            }
            #pragma unroll
            for (int mt = 0; mt < 4; mt++)
                #pragma unroll
                for (int nt = 0; nt < 4; nt++)
                    mma_tf32(acc[mt][nt], af[mt], bf[nt]);
        }
    };

    const int KT = K / 16;
    gload(0);
    sstore(0);
    __syncthreads();

    for (int kt = 0; kt < KT; kt++) {
        int cur = kt & 1;
        if (kt + 1 < KT) gload((kt + 1) * 16);
        compute(cur);
        if (kt + 1 < KT) sstore(cur ^ 1);
        __syncthreads();
    }

    // epilogue
    #pragma unroll
    for (int mt = 0; mt < 4; mt++) {
        int r0 = m0 + wm + mt * 16 + g;
        #pragma unroll
        for (int nt = 0; nt < 4; nt++) {
            int c0 = n0 + wn + nt * 8 + 2 * t;
            float* a4 = acc[mt][nt];
            float2 v0 = {alpha * a4[0], alpha * a4[1]};
            float2 v1 = {alpha * a4[2], alpha * a4[3]};
            if (ADD) {
                float2 d0 = *(const float2*)(Ad + (long long)r0 * ldad + c0);
                float2 d1 = *(const float2*)(Ad + (long long)(r0 + 8) * ldad + c0);
                v0.x += d0.x; v0.y += d0.y;
                v1.x += d1.x; v1.y += d1.y;
            }
            *(float2*)(C + (long long)r0 * ldc + c0) = v0;
            *(float2*)(C + (long long)(r0 + 8) * ldc + c0) = v1;
        }
    }
}

// ============================================================================
// Row softmax over 2048-wide rows. One 256-thread block per row.
// ============================================================================
__global__ __launch_bounds__(256)
void softmax2048(float* __restrict__ S)
{
    float* row = S + (size_t)blockIdx.x * SEQ;
    const int tid = threadIdx.x;

    float vals[8];
    float m = -1e30f;
    #pragma unroll
    for (int i = 0; i < 8; i++) {
        vals[i] = row[tid + i * 256];
        m = fmaxf(m, vals[i]);
    }

    __shared__ float rmax[8];
    __shared__ float rsum[8];

    #pragma unroll
    for (int o = 16; o; o >>= 1) m = fmaxf(m, __shfl_xor_sync(0xffffffffu, m, o));
    if ((tid & 31) == 0) rmax[tid >> 5] = m;
    __syncthreads();
    m = rmax[0];
    #pragma unroll
    for (int w = 1; w < 8; w++) m = fmaxf(m, rmax[w]);

    float s = 0.f;
    #pragma unroll
    for (int i = 0; i < 8; i++) {
        vals[i] = __expf(vals[i] - m);
        s += vals[i];
    }
    #pragma unroll
    for (int o = 16; o; o >>= 1) s += __shfl_xor_sync(0xffffffffu, s, o);
    if ((tid & 31) == 0) rsum[tid >> 5] = s;
    __syncthreads();
    s = rsum[0];
    #pragma unroll
    for (int w = 1; w < 8; w++) s += rsum[w];

    float inv = 1.f / s;
    #pragma unroll
    for (int i = 0; i < 8; i++) row[tid + i * 256] = vals[i] * inv;
}

// ============================================================================
// Highway recurrence: one thread per (b, d) channel across all L steps.
// ============================================================================
__global__ __launch_bounds__(256)
void sru_recur(const float* __restrict__ U, const float* __restrict__ x,
               const float* __restrict__ v, const float* __restrict__ bias,
               float* __restrict__ h)
{
    int tch = blockIdx.x * 256 + threadIdx.x;   // 0 .. NB*DM-1
    int b = tch / DM;
    int d = tch % DM;

    float vf = v[d],    vr = v[DM + d];
    float bf = bias[d], br = bias[DM + d];
    float c = 0.f;

    for (int l = 0; l < SEQ; l++) {
        long long r3 = ((long long)l * NB + b) * (3 * DM) + d;
        long long r1 = ((long long)l * NB + b) * DM + d;
        float xt   = U[r3];
        float fr   = U[r3 + DM];
        float rr   = U[r3 + 2 * DM];
        float xres = x[r1];

        float f = 1.f / (1.f + __expf(-(fr + vf * c + bf)));
        float r = 1.f / (1.f + __expf(-(rr + vr * c + br)));
        c = f * c + (1.f - f) * xt;
        h[r1] = r * c + (1.f - r) * xres;
    }
}

// ============================================================================
// Launch
// ============================================================================
extern "C" void kernel_launch(void* const* d_in, const int* in_sizes, int n_in,
                              void* d_out, int out_size)
{
    const float* x  = (const float*)d_in[0];   // [L,B,1024]
    const float* W1 = (const float*)d_in[1];   // [1024,512]
    const float* W2 = (const float*)d_in[2];   // [512,1024]
    const float* W3 = (const float*)d_in[3];   // [512,3072]
    const float* v  = (const float*)d_in[4];   // [2,1024]
    const float* bb = (const float*)d_in[5];   // [2,1024]
    float* h = (float*)d_out;                  // [L,B,1024]

    float *q, *kv, *sc, *cq, *U;
    cudaGetSymbolAddress((void**)&q,  g_q);
    cudaGetSymbolAddress((void**)&kv, g_kv);
    cudaGetSymbolAddress((void**)&sc, g_scores);
    cudaGetSymbolAddress((void**)&cq, g_cq);
    cudaGetSymbolAddress((void**)&U,  g_U);

    const dim3 T(256);
    const float scale = 1.0f / sqrtf((float)DH);

    // q = x @ W1 : [32768,1024] x [1024,512]
    mma_gemm<false, false><<<dim3(DH / 128, ROWS / 128, 1), T>>>(
        x, W1, q, nullptr, DM, DM, DH, DH, 0, 1.f, 0, 0, 0, 0);

    // kv = q @ W2 : [32768,512] x [512,1024]
    mma_gemm<false, false><<<dim3(2 * DH / 128, ROWS / 128, 1), T>>>(
        q, W2, kv, nullptr, DH, DH, 2 * DH, 2 * DH, 0, 1.f, 0, 0, 0, 0);

    // scores[b] = scale * Q_b @ K_b^T : per-batch [2048,512] x [2048,512]^T
    mma_gemm<true, false><<<dim3(SEQ / 128, SEQ / 128, NB), T>>>(
        q, kv, sc, nullptr, DH, NB * DH, NB * 2 * DH, SEQ, 0, scale,
        (long long)DH, (long long)(2 * DH), (long long)SEQ * SEQ, 0);

    // softmax over rows of 2048
    softmax2048<<<NB * SEQ, 256>>>(sc);

    // cq[b] = attn_b @ Va_b + Q_b : per-batch [2048,2048] x [2048,512]
    mma_gemm<false, true><<<dim3(DH / 128, SEQ / 128, NB), T>>>(
        sc, kv + DH, cq, q, SEQ, SEQ, NB * 2 * DH, NB * DH, NB * DH, 1.f,
        (long long)SEQ * SEQ, (long long)(2 * DH), (long long)DH, (long long)DH);

    // U = cq @ W3 : [32768,512] x [512,3072]
    mma_gemm<false, false><<<dim3(3 * DM / 128, ROWS / 128, 1), T>>>(
        cq, W3, U, nullptr, DH, DH, 3 * DM, 3 * DM, 0, 1.f, 0, 0, 0, 0);

    // elementwise highway recurrence over time
    sru_recur<<<(NB * DM) / 256, 256>>>(U, x, v, bb, h);
}

// round 3
// speedup vs baseline: 4.1222x; 1.3326x over previous
#include <cuda_runtime.h>
#include <math.h>
#include <stdint.h>

#define SEQ 2048
#define NB  16
#define DM  1024
#define DH  512

static constexpr size_t ROWS = (size_t)SEQ * NB;   // 32768

// ---- scratch (device globals; no allocation allowed) ----
__device__ float g_q[ROWS * DH];                    //  64 MB
__device__ float g_kv[ROWS * 2 * DH];               // 128 MB
__device__ float g_scores[(size_t)NB * SEQ * SEQ];  // 256 MB
__device__ float g_cq[ROWS * DH];                   //  64 MB
__device__ float g_U[ROWS * 3 * DM];                // 384 MB
__device__ float g_vaT[(size_t)NB * DH * SEQ];      //  64 MB  va transposed [b][p][l]
__device__ float g_W1T[DH * DM];                    // W1^T [512,1024]
__device__ float g_W2T[DM * DH];                    // W2^T [1024,512]
__device__ float g_W3T[3 * DM * DH];                // W3^T [3072,512]

// ============================================================================
// helpers
// ============================================================================
__device__ __forceinline__ void mma_tf32(float* c, const uint32_t* a, const uint32_t* b) {
    asm volatile(
        "mma.sync.aligned.m16n8k8.row.col.f32.tf32.tf32.f32 "
        "{%0,%1,%2,%3}, {%4,%5,%6,%7}, {%8,%9}, {%0,%1,%2,%3};"
        : "+f"(c[0]), "+f"(c[1]), "+f"(c[2]), "+f"(c[3])
        : "r"(a[0]), "r"(a[1]), "r"(a[2]), "r"(a[3]), "r"(b[0]), "r"(b[1]));
}

__device__ __forceinline__ void ldsm_x4(uint32_t& r0, uint32_t& r1, uint32_t& r2,
                                        uint32_t& r3, uint32_t addr) {
    asm volatile("ldmatrix.sync.aligned.m8n8.x4.shared.b16 {%0,%1,%2,%3}, [%4];"
                 : "=r"(r0), "=r"(r1), "=r"(r2), "=r"(r3) : "r"(addr));
}

__device__ __forceinline__ void cp16(uint32_t smem, const float* g) {
    asm volatile("cp.async.cg.shared.global [%0], [%1], 16;" :: "r"(smem), "l"(g));
}
__device__ __forceinline__ void cp_commit() { asm volatile("cp.async.commit_group;"); }
__device__ __forceinline__ void cp_wait1()  { asm volatile("cp.async.wait_group 1;"); }

// ============================================================================
// TN TF32 GEMM: C[M,N] = alpha * A @ B^T (+ Ad), batched over grid.z.
// A: [M,K] row-major (K contiguous).  B: [N,K] row-major (K contiguous).
// Block tile 128x128x32, 256 threads, warps 2(M)x4(N), warp tile 64x32.
// 3-stage cp.async pipeline; SMEM rows are 128B with xor-swizzled 16B chunks;
// fragments loaded via ldmatrix.x4. fp32 fed raw to tf32 MMA (truncation).
// All dims divide tiles exactly; rows 16B-aligned (static shapes guarantee).
// ============================================================================
#define STAGES 3
#define TILE_BYTES (128 * 32 * 4)   // 16KB per operand per stage

template<bool ADD>
__global__ __launch_bounds__(256)
void gemm_tn(const float* __restrict__ A, const float* __restrict__ B,
             float* __restrict__ C, const float* __restrict__ Ad,
             int K, int lda, int ldb, int ldc, int ldad, float alpha,
             long long sA, long long sB, long long sC, long long sAd)
{
    A += (long long)blockIdx.z * sA;
    B += (long long)blockIdx.z * sB;
    C += (long long)blockIdx.z * sC;
    if (ADD) Ad += (long long)blockIdx.z * sAd;

    extern __shared__ float smem[];
    const uint32_t smem_u32 = (uint32_t)__cvta_generic_to_shared(smem);
    const uint32_t a_base = smem_u32;
    const uint32_t b_base = smem_u32 + STAGES * TILE_BYTES;

    const int m0 = blockIdx.y * 128;
    const int n0 = blockIdx.x * 128;
    const int tid  = threadIdx.x;
    const int lane = tid & 31;
    const int warp = tid >> 5;
    const int wm = (warp >> 2) * 64;
    const int wn = (warp & 3) * 32;

    // ---- loader geometry: 128 rows x 8 chunks(16B) per tile, 4 per thread ----
    int lrow[4], lchk[4];
    uint32_t lsw[4];
    #pragma unroll
    for (int i = 0; i < 4; i++) {
        int id = i * 256 + tid;
        lrow[i] = id >> 3;
        lchk[i] = id & 7;
        lsw[i]  = (uint32_t)(lrow[i] * 128 + ((lchk[i] ^ (lrow[i] & 7)) << 4));
    }

    auto issue = [&](int kt, int buf) {
        const uint32_t ab = a_base + buf * TILE_BYTES;
        const uint32_t bb = b_base + buf * TILE_BYTES;
        const int k0 = kt * 32;
        #pragma unroll
        for (int i = 0; i < 4; i++) {
            cp16(ab + lsw[i], A + (long long)(m0 + lrow[i]) * lda + k0 + lchk[i] * 4);
            cp16(bb + lsw[i], B + (long long)(n0 + lrow[i]) * ldb + k0 + lchk[i] * 4);
        }
    };

    // ---- ldmatrix lane geometry ----
    const int mi = lane >> 3;
    const int lr = lane & 7;
    // A: matrices (mlo,c0)(mhi,c0)(mlo,c1)(mhi,c1)
    const int a_row_in_wtile = (mi & 1) * 8 + lr;     // + mt*16
    const int a_cadd = mi >> 1;
    // B: matrices (nlo,c0)(nlo,c1)(nhi,c0)(nhi,c1)
    const int b_row_in_pair = (mi >> 1) * 8 + lr;     // + np*16
    const int b_cadd = mi & 1;

    float acc[4][4][4];
    #pragma unroll
    for (int mt = 0; mt < 4; mt++)
        #pragma unroll
        for (int nt = 0; nt < 4; nt++)
            #pragma unroll
            for (int r = 0; r < 4; r++) acc[mt][nt][r] = 0.f;

    const int KT = K / 32;
    issue(0, 0); cp_commit();
    issue(1, 1); cp_commit();

    for (int kt = 0; kt < KT; kt++) {
        const int buf = kt % STAGES;
        cp_wait1();
        __syncthreads();           // stage `kt` ready; all warps done with buf (kt+2)%STAGES

        if (kt + 2 < KT) issue(kt + 2, (kt + 2) % STAGES);
        cp_commit();               // empty commits keep wait_group accounting correct

        const uint32_t ab = a_base + buf * TILE_BYTES;
        const uint32_t bb = b_base + buf * TILE_BYTES;

        #pragma unroll
        for (int s = 0; s < 4; s++) {
            uint32_t af[4][4], bf[4][2];
            #pragma unroll
            for (int mt = 0; mt < 4; mt++) {
                int m = wm + mt * 16 + a_row_in_wtile;
                int c = s * 2 + a_cadd;
                ldsm_x4(af[mt][0], af[mt][1], af[mt][2], af[mt][3],
                        ab + m * 128 + ((c ^ (m & 7)) << 4));
            }
            #pragma unroll
            for (int np = 0; np < 2; np++) {
                int n = wn + np * 16 + b_row_in_pair;
                int c = s * 2 + b_cadd;
                ldsm_x4(bf[2 * np][0], bf[2 * np][1], bf[2 * np + 1][0], bf[2 * np + 1][1],
                        bb + n * 128 + ((c ^ (n & 7)) << 4));
            }
            #pragma unroll
            for (int mt = 0; mt < 4; mt++)
                #pragma unroll
                for (int nt = 0; nt < 4; nt++)
                    mma_tf32(acc[mt][nt], af[mt], bf[nt]);
        }
    }

    // ---- epilogue ----
    const int g = lane >> 2;
    const int t = lane & 3;
    #pragma unroll
    for (int mt = 0; mt < 4; mt++) {
        int r0 = m0 + wm + mt * 16 + g;
        #pragma unroll
        for (int nt = 0; nt < 4; nt++) {
            int c0 = n0 + wn + nt * 8 + 2 * t;
            float* a4 = acc[mt][nt];
            float2 v0 = {alpha * a4[0], alpha * a4[1]};
            float2 v1 = {alpha * a4[2], alpha * a4[3]};
            if (ADD) {
                float2 d0 = *(const float2*)(Ad + (long long)r0 * ldad + c0);
                float2 d1 = *(const float2*)(Ad + (long long)(r0 + 8) * ldad + c0);
                v0.x += d0.x; v0.y += d0.y;
                v1.x += d1.x; v1.y += d1.y;
            }
            *(float2*)(C + (long long)r0 * ldc + c0) = v0;
            *(float2*)(C + (long long)(r0 + 8) * ldc + c0) = v1;
        }
    }
}

// ============================================================================
// Tiled transpose: out[c][r] = in[r][c].  R,C multiples of 32.
// in rows have stride ld_in; out rows stride ld_out. Batched via grid.z.
// ============================================================================
__global__ __launch_bounds__(256)
void transpose_k(const float* __restrict__ in, float* __restrict__ out,
                 int R, int C, long long ld_in, long long ld_out,
                 long long sIn, long long sOut)
{
    in  += (long long)blockIdx.z * sIn;
    out += (long long)blockIdx.z * sOut;
    __shared__ float tile[32][33];
    const int rb = blockIdx.y * 32;
    const int cb = blockIdx.x * 32;
    const int tx = threadIdx.x & 31;
    const int ty = threadIdx.x >> 5;   // 0..7
    #pragma unroll
    for (int i = 0; i < 4; i++)
        tile[ty + i * 8][tx] = in[(long long)(rb + ty + i * 8) * ld_in + cb + tx];
    __syncthreads();
    #pragma unroll
    for (int i = 0; i < 4; i++)
        out[(long long)(cb + ty + i * 8) * ld_out + rb + tx] = tile[tx][ty + i * 8];
}

// ============================================================================
// Row softmax over 2048-wide rows.
// ============================================================================
__global__ __launch_bounds__(256)
void softmax2048(float* __restrict__ S)
{
    float* row = S + (size_t)blockIdx.x * SEQ;
    const int tid = threadIdx.x;

    float vals[8];
    float m = -1e30f;
    #pragma unroll
    for (int i = 0; i < 8; i++) {
        vals[i] = row[tid + i * 256];
        m = fmaxf(m, vals[i]);
    }

    __shared__ float rmax[8];
    __shared__ float rsum[8];

    #pragma unroll
    for (int o = 16; o; o >>= 1) m = fmaxf(m, __shfl_xor_sync(0xffffffffu, m, o));
    if ((tid & 31) == 0) rmax[tid >> 5] = m;
    __syncthreads();
    m = rmax[0];
    #pragma unroll
    for (int w = 1; w < 8; w++) m = fmaxf(m, rmax[w]);

    float s = 0.f;
    #pragma unroll
    for (int i = 0; i < 8; i++) {
        vals[i] = __expf(vals[i] - m);
        s += vals[i];
    }
    #pragma unroll
    for (int o = 16; o; o >>= 1) s += __shfl_xor_sync(0xffffffffu, s, o);
    if ((tid & 31) == 0) rsum[tid >> 5] = s;
    __syncthreads();
    s = rsum[0];
    #pragma unroll
    for (int w = 1; w < 8; w++) s += rsum[w];

    float inv = 1.f / s;
    #pragma unroll
    for (int i = 0; i < 8; i++) row[tid + i * 256] = vals[i] * inv;
}

// ============================================================================
// Highway recurrence: one thread per (b, d) channel across all L steps.
// ============================================================================
__global__ __launch_bounds__(256)
void sru_recur(const float* __restrict__ U, const float* __restrict__ x,
               const float* __restrict__ v, const float* __restrict__ bias,
               float* __restrict__ h)
{
    int tch = blockIdx.x * 256 + threadIdx.x;
    int b = tch / DM;
    int d = tch % DM;

    float vf = v[d],    vr = v[DM + d];
    float bf = bias[d], br = bias[DM + d];
    float c = 0.f;

    for (int l = 0; l < SEQ; l++) {
        long long r3 = ((long long)l * NB + b) * (3 * DM) + d;
        long long r1 = ((long long)l * NB + b) * DM + d;
        float xt   = U[r3];
        float fr   = U[r3 + DM];
        float rr   = U[r3 + 2 * DM];
        float xres = x[r1];

        float f = 1.f / (1.f + __expf(-(fr + vf * c + bf)));
        float r = 1.f / (1.f + __expf(-(rr + vr * c + br)));
        c = f * c + (1.f - f) * xt;
        h[r1] = r * c + (1.f - r) * xres;
    }
}

// ============================================================================
// Launch
// ============================================================================
extern "C" void kernel_launch(void* const* d_in, const int* in_sizes, int n_in,
                              void* d_out, int out_size)
{
    const float* x  = (const float*)d_in[0];
    const float* W1 = (const float*)d_in[1];   // [1024,512]
    const float* W2 = (const float*)d_in[2];   // [512,1024]
    const float* W3 = (const float*)d_in[3];   // [512,3072]
    const float* v  = (const float*)d_in[4];
    const float* bb = (const float*)d_in[5];
    float* h = (float*)d_out;

    float *q, *kv, *sc, *cq, *U, *vaT, *W1T, *W2T, *W3T;
    cudaGetSymbolAddress((void**)&q,   g_q);
    cudaGetSymbolAddress((void**)&kv,  g_kv);
    cudaGetSymbolAddress((void**)&sc,  g_scores);
    cudaGetSymbolAddress((void**)&cq,  g_cq);
    cudaGetSymbolAddress((void**)&U,   g_U);
    cudaGetSymbolAddress((void**)&vaT, g_vaT);
    cudaGetSymbolAddress((void**)&W1T, g_W1T);
    cudaGetSymbolAddress((void**)&W2T, g_W2T);
    cudaGetSymbolAddress((void**)&W3T, g_W3T);

    const int smem_bytes = STAGES * 2 * TILE_BYTES;   // 96KB
    cudaFuncSetAttribute(gemm_tn<false>, cudaFuncAttributeMaxDynamicSharedMemorySize, smem_bytes);
    cudaFuncSetAttribute(gemm_tn<true>,  cudaFuncAttributeMaxDynamicSharedMemorySize, smem_bytes);

    const dim3 T(256);
    const float scale = 1.0f / sqrtf((float)DH);

    // weight transposes (TN form wants B as [N,K])
    transpose_k<<<dim3(DH / 32, DM / 32, 1), T>>>(W1, W1T, DM, DH, DH, DM, 0, 0);
    transpose_k<<<dim3(DM / 32, DH / 32, 1), T>>>(W2, W2T, DH, DM, DM, DH, 0, 0);
    transpose_k<<<dim3(3 * DM / 32, DH / 32, 1), T>>>(W3, W3T, DH, 3 * DM, 3 * DM, DH, 0, 0);

    // q = x @ W1 : A=x [32768,1024], B=W1T [512,1024]
    gemm_tn<false><<<dim3(DH / 128, ROWS / 128, 1), T, smem_bytes>>>(
        x, W1T, q, nullptr, DM, DM, DM, DH, 0, 1.f, 0, 0, 0, 0);

    // kv = q @ W2 : A=q [32768,512], B=W2T [1024,512]
    gemm_tn<false><<<dim3(2 * DH / 128, ROWS / 128, 1), T, smem_bytes>>>(
        q, W2T, kv, nullptr, DH, DH, DH, 2 * DH, 0, 1.f, 0, 0, 0, 0);

    // scores[b] = scale * Q_b @ K_b^T : A=q rows (stride NB*DH), B=k rows (stride NB*2DH)
    gemm_tn<false><<<dim3(SEQ / 128, SEQ / 128, NB), T, smem_bytes>>>(
        q, kv, sc, nullptr, DH, NB * DH, NB * 2 * DH, SEQ, 0, scale,
        (long long)DH, (long long)(2 * DH), (long long)SEQ * SEQ, 0);

    softmax2048<<<NB * SEQ, 256>>>(sc);

    // vaT[b][p][l] = kv[l][b][DH + p]
    transpose_k<<<dim3(DH / 32, SEQ / 32, NB), T>>>(
        kv + DH, vaT, SEQ, DH, (long long)NB * 2 * DH, SEQ,
        (long long)(2 * DH), (long long)DH * SEQ);

    // cq[b] = attn_b @ vaT_b^T + Q_b : A=attn [2048,2048], B=vaT [512,2048]
    gemm_tn<true><<<dim3(DH / 128, SEQ / 128, NB), T, smem_bytes>>>(
        sc, vaT, cq, q, SEQ, SEQ, SEQ, NB * DH, NB * DH, 1.f,
        (long long)SEQ * SEQ, (long long)DH * SEQ, (long long)DH, (long long)DH);

    // U = cq @ W3 : A=cq [32768,512], B=W3T [3072,512]
    gemm_tn<false><<<dim3(3 * DM / 128, ROWS / 128, 1), T, smem_bytes>>>(
        cq, W3T, U, nullptr, DH, DH, DH, 3 * DM, 0, 1.f, 0, 0, 0, 0);

    sru_recur<<<(NB * DM) / 256, 256>>>(U, x, v, bb, h);
}

// round 4
// speedup vs baseline: 6.1725x; 1.4974x over previous
#include <cuda_runtime.h>
#include <math.h>
#include <stdint.h>

#define SEQ 2048
#define NB  16
#define DM  1024
#define DH  512

static constexpr size_t ROWS = (size_t)SEQ * NB;   // 32768

// ---- scratch (device globals; no allocation allowed) ----
__device__ float g_q[ROWS * DH];                    //  64 MB
__device__ float g_kv[ROWS * 2 * DH];               // 128 MB
__device__ float g_scores[(size_t)NB * SEQ * SEQ];  // 256 MB
__device__ float g_cq[ROWS * DH];                   //  64 MB
__device__ float g_U[ROWS * 3 * DM];                // 384 MB
__device__ float g_vaT[(size_t)NB * DH * SEQ];      //  64 MB
__device__ float g_W1T[DH * DM];
__device__ float g_W2T[DM * DH];
__device__ float g_W3T[3 * DM * DH];

// ============================================================================
// helpers
// ============================================================================
__device__ __forceinline__ void mma_tf32(float* c, const uint32_t* a, const uint32_t* b) {
    asm volatile(
        "mma.sync.aligned.m16n8k8.row.col.f32.tf32.tf32.f32 "
        "{%0,%1,%2,%3}, {%4,%5,%6,%7}, {%8,%9}, {%0,%1,%2,%3};"
        : "+f"(c[0]), "+f"(c[1]), "+f"(c[2]), "+f"(c[3])
        : "r"(a[0]), "r"(a[1]), "r"(a[2]), "r"(a[3]), "r"(b[0]), "r"(b[1]));
}

__device__ __forceinline__ void ldsm_x4(uint32_t& r0, uint32_t& r1, uint32_t& r2,
                                        uint32_t& r3, uint32_t addr) {
    asm volatile("ldmatrix.sync.aligned.m8n8.x4.shared.b16 {%0,%1,%2,%3}, [%4];"
                 : "=r"(r0), "=r"(r1), "=r"(r2), "=r"(r3) : "r"(addr));
}

__device__ __forceinline__ void cp16(uint32_t smem, const float* g) {
    asm volatile("cp.async.cg.shared.global [%0], [%1], 16;" :: "r"(smem), "l"(g));
}
__device__ __forceinline__ void cp_commit() { asm volatile("cp.async.commit_group;"); }
__device__ __forceinline__ void cp_wait1()  { asm volatile("cp.async.wait_group 1;"); }

// ============================================================================
// TN TF32 GEMM: C[M,N] = alpha * A @ B^T (+ Ad), batched over grid.z.
// Block tile 128x128x32, 256 threads, 3-stage cp.async, ldmatrix.x4 fragments.
// ============================================================================
#define STAGES 3
#define TILE_BYTES (128 * 32 * 4)

template<bool ADD>
__global__ __launch_bounds__(256)
void gemm_tn(const float* __restrict__ A, const float* __restrict__ B,
             float* __restrict__ C, const float* __restrict__ Ad,
             int K, int lda, int ldb, int ldc, int ldad, float alpha,
             long long sA, long long sB, long long sC, long long sAd)
{
    A += (long long)blockIdx.z * sA;
    B += (long long)blockIdx.z * sB;
    C += (long long)blockIdx.z * sC;
    if (ADD) Ad += (long long)blockIdx.z * sAd;

    extern __shared__ float smem[];
    const uint32_t smem_u32 = (uint32_t)__cvta_generic_to_shared(smem);
    const uint32_t a_base = smem_u32;
    const uint32_t b_base = smem_u32 + STAGES * TILE_BYTES;

    const int m0 = blockIdx.y * 128;
    const int n0 = blockIdx.x * 128;
    const int tid  = threadIdx.x;
    const int lane = tid & 31;
    const int warp = tid >> 5;
    const int wm = (warp >> 2) * 64;
    const int wn = (warp & 3) * 32;

    int lrow[4], lchk[4];
    uint32_t lsw[4];
    #pragma unroll
    for (int i = 0; i < 4; i++) {
        int id = i * 256 + tid;
        lrow[i] = id >> 3;
        lchk[i] = id & 7;
        lsw[i]  = (uint32_t)(lrow[i] * 128 + ((lchk[i] ^ (lrow[i] & 7)) << 4));
    }

    auto issue = [&](int kt, int buf) {
        const uint32_t ab = a_base + buf * TILE_BYTES;
        const uint32_t bb = b_base + buf * TILE_BYTES;
        const int k0 = kt * 32;
        #pragma unroll
        for (int i = 0; i < 4; i++) {
            cp16(ab + lsw[i], A + (long long)(m0 + lrow[i]) * lda + k0 + lchk[i] * 4);
            cp16(bb + lsw[i], B + (long long)(n0 + lrow[i]) * ldb + k0 + lchk[i] * 4);
        }
    };

    const int mi = lane >> 3;
    const int lr = lane & 7;
    const int a_row_in_wtile = (mi & 1) * 8 + lr;
    const int a_cadd = mi >> 1;
    const int b_row_in_pair = (mi >> 1) * 8 + lr;
    const int b_cadd = mi & 1;

    float acc[4][4][4];
    #pragma unroll
    for (int mt = 0; mt < 4; mt++)
        #pragma unroll
        for (int nt = 0; nt < 4; nt++)
            #pragma unroll
            for (int r = 0; r < 4; r++) acc[mt][nt][r] = 0.f;

    const int KT = K / 32;
    issue(0, 0); cp_commit();
    issue(1, 1); cp_commit();

    for (int kt = 0; kt < KT; kt++) {
        const int buf = kt % STAGES;
        cp_wait1();
        __syncthreads();

        if (kt + 2 < KT) issue(kt + 2, (kt + 2) % STAGES);
        cp_commit();

        const uint32_t ab = a_base + buf * TILE_BYTES;
        const uint32_t bb = b_base + buf * TILE_BYTES;

        #pragma unroll
        for (int s = 0; s < 4; s++) {
            uint32_t af[4][4], bf[4][2];
            #pragma unroll
            for (int mt = 0; mt < 4; mt++) {
                int m = wm + mt * 16 + a_row_in_wtile;
                int c = s * 2 + a_cadd;
                ldsm_x4(af[mt][0], af[mt][1], af[mt][2], af[mt][3],
                        ab + m * 128 + ((c ^ (m & 7)) << 4));
            }
            #pragma unroll
            for (int np = 0; np < 2; np++) {
                int n = wn + np * 16 + b_row_in_pair;
                int c = s * 2 + b_cadd;
                ldsm_x4(bf[2 * np][0], bf[2 * np][1], bf[2 * np + 1][0], bf[2 * np + 1][1],
                        bb + n * 128 + ((c ^ (n & 7)) << 4));
            }
            #pragma unroll
            for (int mt = 0; mt < 4; mt++)
                #pragma unroll
                for (int nt = 0; nt < 4; nt++)
                    mma_tf32(acc[mt][nt], af[mt], bf[nt]);
        }
    }

    const int g = lane >> 2;
    const int t = lane & 3;
    #pragma unroll
    for (int mt = 0; mt < 4; mt++) {
        int r0 = m0 + wm + mt * 16 + g;
        #pragma unroll
        for (int nt = 0; nt < 4; nt++) {
            int c0 = n0 + wn + nt * 8 + 2 * t;
            float* a4 = acc[mt][nt];
            float2 v0 = {alpha * a4[0], alpha * a4[1]};
            float2 v1 = {alpha * a4[2], alpha * a4[3]};
            if (ADD) {
                float2 d0 = *(const float2*)(Ad + (long long)r0 * ldad + c0);
                float2 d1 = *(const float2*)(Ad + (long long)(r0 + 8) * ldad + c0);
                v0.x += d0.x; v0.y += d0.y;
                v1.x += d1.x; v1.y += d1.y;
            }
            *(float2*)(C + (long long)r0 * ldc + c0) = v0;
            *(float2*)(C + (long long)(r0 + 8) * ldc + c0) = v1;
        }
    }
}

// ============================================================================
// Tiled transpose (batched)
// ============================================================================
__global__ __launch_bounds__(256)
void transpose_k(const float* __restrict__ in, float* __restrict__ out,
                 int R, int C, long long ld_in, long long ld_out,
                 long long sIn, long long sOut)
{
    in  += (long long)blockIdx.z * sIn;
    out += (long long)blockIdx.z * sOut;
    __shared__ float tile[32][33];
    const int rb = blockIdx.y * 32;
    const int cb = blockIdx.x * 32;
    const int tx = threadIdx.x & 31;
    const int ty = threadIdx.x >> 5;
    #pragma unroll
    for (int i = 0; i < 4; i++)
        tile[ty + i * 8][tx] = in[(long long)(rb + ty + i * 8) * ld_in + cb + tx];
    __syncthreads();
    #pragma unroll
    for (int i = 0; i < 4; i++)
        out[(long long)(cb + ty + i * 8) * ld_out + rb + tx] = tile[tx][ty + i * 8];
}

// ============================================================================
// Row softmax over 2048-wide rows.
// ============================================================================
__global__ __launch_bounds__(256)
void softmax2048(float* __restrict__ S)
{
    float* row = S + (size_t)blockIdx.x * SEQ;
    const int tid = threadIdx.x;

    float vals[8];
    float m = -1e30f;
    #pragma unroll
    for (int i = 0; i < 8; i++) {
        vals[i] = row[tid + i * 256];
        m = fmaxf(m, vals[i]);
    }

    __shared__ float rmax[8];
    __shared__ float rsum[8];

    #pragma unroll
    for (int o = 16; o; o >>= 1) m = fmaxf(m, __shfl_xor_sync(0xffffffffu, m, o));
    if ((tid & 31) == 0) rmax[tid >> 5] = m;
    __syncthreads();
    m = rmax[0];
    #pragma unroll
    for (int w = 1; w < 8; w++) m = fmaxf(m, rmax[w]);

    float s = 0.f;
    #pragma unroll
    for (int i = 0; i < 8; i++) {
        vals[i] = __expf(vals[i] - m);
        s += vals[i];
    }
    #pragma unroll
    for (int o = 16; o; o >>= 1) s += __shfl_xor_sync(0xffffffffu, s, o);
    if ((tid & 31) == 0) rsum[tid >> 5] = s;
    __syncthreads();
    s = rsum[0];
    #pragma unroll
    for (int w = 1; w < 8; w++) s += rsum[w];

    float inv = 1.f / s;
    #pragma unroll
    for (int i = 0; i < 8; i++) row[tid + i * 256] = vals[i] * inv;
}

// ============================================================================
// Highway recurrence with per-warp cp.async ring buffer (depth 16).
// Each warp owns 32 consecutive channels; lanes cooperatively prefetch
// 16 timesteps ahead (one 16B chunk per lane per step). Only warp-level
// synchronization — memory latency fully decoupled from the serial chain.
// ============================================================================
#define RDEPTH 16   // stages; per-warp stage = 4 arrays x 32 floats = 512B

__global__ __launch_bounds__(256)
void sru_recur2(const float* __restrict__ U, const float* __restrict__ x,
                const float* __restrict__ v, const float* __restrict__ bias,
                float* __restrict__ h)
{
    extern __shared__ float rbuf[];   // [8 warps][RDEPTH][4][32]
    const int tid  = threadIdx.x;
    const int lane = tid & 31;
    const int warp = tid >> 5;

    const int ch  = blockIdx.x * 256 + tid;       // channel = b*DM + d
    const int b   = ch / DM;
    const int d   = ch % DM;
    const int d0w = (blockIdx.x * 256 + warp * 32) % DM;  // warp's d base

    // producer mapping: lane -> (array, 16B chunk)
    const int arr = lane >> 3;        // 0:x_tilde 1:f_raw 2:r_raw 3:x
    const int c4  = (lane & 7) * 4;   // float offset within 32-channel slice
    const float* src;
    long long stride;
    if (arr < 3) {
        src = U + (long long)b * 3 * DM + (long long)arr * DM + d0w + c4;
        stride = (long long)NB * 3 * DM;
    } else {
        src = x + (long long)b * DM + d0w + c4;
        stride = (long long)NB * DM;
    }

    const uint32_t wbase = (uint32_t)__cvta_generic_to_shared(rbuf) + warp * RDEPTH * 512;

    // prefill RDEPTH stages (one commit group per stage)
    #pragma unroll
    for (int s = 0; s < RDEPTH; s++) {
        cp16(wbase + s * 512 + lane * 16, src);
        src += stride;
        cp_commit();
    }

    const float vf = v[d],    vr = v[DM + d];
    const float bf = bias[d], br = bias[DM + d];
    float c = 0.f;
    float* hp = h + (long long)b * DM + d;
    const long long hstride = (long long)NB * DM;
    const float* warp_smem = rbuf + warp * RDEPTH * 128;

    for (int l = 0; l < SEQ; l++) {
        const int st = l & (RDEPTH - 1);
        asm volatile("cp.async.wait_group %0;" :: "n"(RDEPTH - 1));
        __syncwarp();
        float xt   = warp_smem[st * 128 + 0 * 32 + lane];
        float fr   = warp_smem[st * 128 + 1 * 32 + lane];
        float rr   = warp_smem[st * 128 + 2 * 32 + lane];
        float xres = warp_smem[st * 128 + 3 * 32 + lane];
        __syncwarp();
        if (l + RDEPTH < SEQ) { cp16(wbase + st * 512 + lane * 16, src); src += stride; }
        cp_commit();   // empty groups keep wait_group accounting exact

        float f = 1.f / (1.f + __expf(-(fr + vf * c + bf)));
        float r = 1.f / (1.f + __expf(-(rr + vr * c + br)));
        c = f * c + (1.f - f) * xt;
        hp[0] = r * c + (1.f - r) * xres;
        hp += hstride;
    }
}

// ============================================================================
// Launch
// ============================================================================
extern "C" void kernel_launch(void* const* d_in, const int* in_sizes, int n_in,
                              void* d_out, int out_size)
{
    const float* x  = (const float*)d_in[0];
    const float* W1 = (const float*)d_in[1];
    const float* W2 = (const float*)d_in[2];
    const float* W3 = (const float*)d_in[3];
    const float* v  = (const float*)d_in[4];
    const float* bb = (const float*)d_in[5];
    float* h = (float*)d_out;

    float *q, *kv, *sc, *cq, *U, *vaT, *W1T, *W2T, *W3T;
    cudaGetSymbolAddress((void**)&q,   g_q);
    cudaGetSymbolAddress((void**)&kv,  g_kv);
    cudaGetSymbolAddress((void**)&sc,  g_scores);
    cudaGetSymbolAddress((void**)&cq,  g_cq);
    cudaGetSymbolAddress((void**)&U,   g_U);
    cudaGetSymbolAddress((void**)&vaT, g_vaT);
    cudaGetSymbolAddress((void**)&W1T, g_W1T);
    cudaGetSymbolAddress((void**)&W2T, g_W2T);
    cudaGetSymbolAddress((void**)&W3T, g_W3T);

    const int smem_bytes = STAGES * 2 * TILE_BYTES;        // 96KB
    const int rec_smem   = 8 * RDEPTH * 4 * 32 * 4;        // 64KB
    cudaFuncSetAttribute(gemm_tn<false>, cudaFuncAttributeMaxDynamicSharedMemorySize, smem_bytes);
    cudaFuncSetAttribute(gemm_tn<true>,  cudaFuncAttributeMaxDynamicSharedMemorySize, smem_bytes);
    cudaFuncSetAttribute(sru_recur2,     cudaFuncAttributeMaxDynamicSharedMemorySize, rec_smem);

    const dim3 T(256);
    const float scale = 1.0f / sqrtf((float)DH);

    transpose_k<<<dim3(DH / 32, DM / 32, 1), T>>>(W1, W1T, DM, DH, DH, DM, 0, 0);
    transpose_k<<<dim3(DM / 32, DH / 32, 1), T>>>(W2, W2T, DH, DM, DM, DH, 0, 0);
    transpose_k<<<dim3(3 * DM / 32, DH / 32, 1), T>>>(W3, W3T, DH, 3 * DM, 3 * DM, DH, 0, 0);

    gemm_tn<false><<<dim3(DH / 128, ROWS / 128, 1), T, smem_bytes>>>(
        x, W1T, q, nullptr, DM, DM, DM, DH, 0, 1.f, 0, 0, 0, 0);

    gemm_tn<false><<<dim3(2 * DH / 128, ROWS / 128, 1), T, smem_bytes>>>(
        q, W2T, kv, nullptr, DH, DH, DH, 2 * DH, 0, 1.f, 0, 0, 0, 0);

    gemm_tn<false><<<dim3(SEQ / 128, SEQ / 128, NB), T, smem_bytes>>>(
        q, kv, sc, nullptr, DH, NB * DH, NB * 2 * DH, SEQ, 0, scale,
        (long long)DH, (long long)(2 * DH), (long long)SEQ * SEQ, 0);

    softmax2048<<<NB * SEQ, 256>>>(sc);

    transpose_k<<<dim3(DH / 32, SEQ / 32, NB), T>>>(
        kv + DH, vaT, SEQ, DH, (long long)NB * 2 * DH, SEQ,
        (long long)(2 * DH), (long long)DH * SEQ);

    gemm_tn<true><<<dim3(DH / 128, SEQ / 128, NB), T, smem_bytes>>>(
        sc, vaT, cq, q, SEQ, SEQ, SEQ, NB * DH, NB * DH, 1.f,
        (long long)SEQ * SEQ, (long long)DH * SEQ, (long long)DH, (long long)DH);

    gemm_tn<false><<<dim3(3 * DM / 128, ROWS / 128, 1), T, smem_bytes>>>(
        cq, W3T, U, nullptr, DH, DH, DH, 3 * DM, 0, 1.f, 0, 0, 0, 0);

    sru_recur2<<<(NB * DM) / 256, 256, rec_smem>>>(U, x, v, bb, h);
}

// round 5
// speedup vs baseline: 6.4299x; 1.0417x over previous
#include <cuda_runtime.h>
#include <math.h>
#include <stdint.h>

#define SEQ 2048
#define NB  16
#define DM  1024
#define DH  512

static constexpr size_t ROWS = (size_t)SEQ * NB;   // 32768

// ---- scratch (device globals; no allocation allowed) ----
__device__ float g_q[ROWS * DH];                    //  64 MB
__device__ float g_kv[ROWS * 2 * DH];               // 128 MB
__device__ float g_scores[(size_t)NB * SEQ * SEQ];  // 256 MB
__device__ float g_cq[ROWS * DH];                   //  64 MB
__device__ float g_U[ROWS * 3 * DM];                // 384 MB
__device__ float g_vaT[(size_t)NB * DH * SEQ];      //  64 MB
__device__ float g_W1T[DH * DM];
__device__ float g_W2T[DM * DH];
__device__ float g_W3T[3 * DM * DH];

// ============================================================================
// helpers
// ============================================================================
__device__ __forceinline__ void mma_tf32(float* c, const uint32_t* a, const uint32_t* b) {
    asm volatile(
        "mma.sync.aligned.m16n8k8.row.col.f32.tf32.tf32.f32 "
        "{%0,%1,%2,%3}, {%4,%5,%6,%7}, {%8,%9}, {%0,%1,%2,%3};"
        : "+f"(c[0]), "+f"(c[1]), "+f"(c[2]), "+f"(c[3])
        : "r"(a[0]), "r"(a[1]), "r"(a[2]), "r"(a[3]), "r"(b[0]), "r"(b[1]));
}

__device__ __forceinline__ void ldsm_x4(uint32_t& r0, uint32_t& r1, uint32_t& r2,
                                        uint32_t& r3, uint32_t addr) {
    asm volatile("ldmatrix.sync.aligned.m8n8.x4.shared.b16 {%0,%1,%2,%3}, [%4];"
                 : "=r"(r0), "=r"(r1), "=r"(r2), "=r"(r3) : "r"(addr));
}

__device__ __forceinline__ void cp16(uint32_t smem, const float* g) {
    asm volatile("cp.async.cg.shared.global [%0], [%1], 16;" :: "r"(smem), "l"(g));
}
__device__ __forceinline__ void cp_commit() { asm volatile("cp.async.commit_group;"); }
__device__ __forceinline__ void cp_wait1()  { asm volatile("cp.async.wait_group 1;"); }

// ============================================================================
// TN TF32 GEMM: C[M,N] = alpha * A @ B^T (+ Ad), batched over grid.z.
// Block tile 128x128x32, 128 threads, warps 2x2, warp tile 64x64.
// 3-stage cp.async pipeline, ldmatrix.x4 fragments double-buffered across
// 8-K slices. MMA:LDSM ratio = 4. 2 CTAs/SM.
// ============================================================================
#define STAGES 3
#define TILE_BYTES (128 * 32 * 4)

template<bool ADD>
__global__ __launch_bounds__(128, 2)
void gemm_tn(const float* __restrict__ A, const float* __restrict__ B,
             float* __restrict__ C, const float* __restrict__ Ad,
             int K, int lda, int ldb, int ldc, int ldad, float alpha,
             long long sA, long long sB, long long sC, long long sAd)
{
    A += (long long)blockIdx.z * sA;
    B += (long long)blockIdx.z * sB;
    C += (long long)blockIdx.z * sC;
    if (ADD) Ad += (long long)blockIdx.z * sAd;

    extern __shared__ float smem[];
    const uint32_t smem_u32 = (uint32_t)__cvta_generic_to_shared(smem);
    const uint32_t a_base = smem_u32;
    const uint32_t b_base = smem_u32 + STAGES * TILE_BYTES;

    const int m0 = blockIdx.y * 128;
    const int n0 = blockIdx.x * 128;
    const int tid  = threadIdx.x;
    const int lane = tid & 31;
    const int warp = tid >> 5;
    const int wm = (warp >> 1) * 64;
    const int wn = (warp & 1) * 64;

    // ---- loader geometry: 128 rows x 8 chunks(16B) per tile, 8 per thread ----
    int lrow[8], lchk[8];
    uint32_t lsw[8];
    #pragma unroll
    for (int i = 0; i < 8; i++) {
        int id = i * 128 + tid;
        lrow[i] = id >> 3;
        lchk[i] = id & 7;
        lsw[i]  = (uint32_t)(lrow[i] * 128 + ((lchk[i] ^ (lrow[i] & 7)) << 4));
    }

    auto issue = [&](int kt, int buf) {
        const uint32_t ab = a_base + buf * TILE_BYTES;
        const uint32_t bb = b_base + buf * TILE_BYTES;
        const int k0 = kt * 32;
        #pragma unroll
        for (int i = 0; i < 8; i++)
            cp16(ab + lsw[i], A + (long long)(m0 + lrow[i]) * lda + k0 + lchk[i] * 4);
        #pragma unroll
        for (int i = 0; i < 8; i++)
            cp16(bb + lsw[i], B + (long long)(n0 + lrow[i]) * ldb + k0 + lchk[i] * 4);
    };

    // ---- ldmatrix lane geometry ----
    const int mi = lane >> 3;
    const int lr = lane & 7;
    const int a_row_in_wtile = (mi & 1) * 8 + lr;   // + mt*16
    const int a_cadd = mi >> 1;
    const int b_row_in_pair = (mi >> 1) * 8 + lr;   // + np*16
    const int b_cadd = mi & 1;

    float acc[4][8][4];
    #pragma unroll
    for (int mt = 0; mt < 4; mt++)
        #pragma unroll
        for (int nt = 0; nt < 8; nt++)
            #pragma unroll
            for (int r = 0; r < 4; r++) acc[mt][nt][r] = 0.f;

    // double-buffered fragments
    uint32_t af[2][4][4], bf[2][8][2];

    auto load_frags = [&](uint32_t ab, uint32_t bb, int s, int pb) {
        #pragma unroll
        for (int mt = 0; mt < 4; mt++) {
            int m = wm + mt * 16 + a_row_in_wtile;
            int c = s * 2 + a_cadd;
            ldsm_x4(af[pb][mt][0], af[pb][mt][1], af[pb][mt][2], af[pb][mt][3],
                    ab + m * 128 + ((c ^ (m & 7)) << 4));
        }
        #pragma unroll
        for (int np = 0; np < 4; np++) {
            int n = wn + np * 16 + b_row_in_pair;
            int c = s * 2 + b_cadd;
            ldsm_x4(bf[pb][2 * np][0], bf[pb][2 * np][1],
                    bf[pb][2 * np + 1][0], bf[pb][2 * np + 1][1],
                    bb + n * 128 + ((c ^ (n & 7)) << 4));
        }
    };

    const int KT = K / 32;
    issue(0, 0); cp_commit();
    issue(1, 1); cp_commit();

    for (int kt = 0; kt < KT; kt++) {
        const int buf = kt % STAGES;
        cp_wait1();
        __syncthreads();

        if (kt + 2 < KT) issue(kt + 2, (kt + 2) % STAGES);
        cp_commit();

        const uint32_t ab = a_base + buf * TILE_BYTES;
        const uint32_t bb = b_base + buf * TILE_BYTES;

        load_frags(ab, bb, 0, 0);
        #pragma unroll
        for (int s = 0; s < 4; s++) {
            const int pb = s & 1;
            if (s < 3) load_frags(ab, bb, s + 1, pb ^ 1);
            #pragma unroll
            for (int mt = 0; mt < 4; mt++)
                #pragma unroll
                for (int nt = 0; nt < 8; nt++)
                    mma_tf32(acc[mt][nt], af[pb][mt], bf[pb][nt]);
        }
    }

    // ---- epilogue ----
    const int g = lane >> 2;
    const int t = lane & 3;
    #pragma unroll
    for (int mt = 0; mt < 4; mt++) {
        int r0 = m0 + wm + mt * 16 + g;
        #pragma unroll
        for (int nt = 0; nt < 8; nt++) {
            int c0 = n0 + wn + nt * 8 + 2 * t;
            float* a4 = acc[mt][nt];
            float2 v0 = {alpha * a4[0], alpha * a4[1]};
            float2 v1 = {alpha * a4[2], alpha * a4[3]};
            if (ADD) {
                float2 d0 = *(const float2*)(Ad + (long long)r0 * ldad + c0);
                float2 d1 = *(const float2*)(Ad + (long long)(r0 + 8) * ldad + c0);
                v0.x += d0.x; v0.y += d0.y;
                v1.x += d1.x; v1.y += d1.y;
            }
            *(float2*)(C + (long long)r0 * ldc + c0) = v0;
            *(float2*)(C + (long long)(r0 + 8) * ldc + c0) = v1;
        }
    }
}

// ============================================================================
// Tiled transpose (batched)
// ============================================================================
__global__ __launch_bounds__(256)
void transpose_k(const float* __restrict__ in, float* __restrict__ out,
                 int R, int C, long long ld_in, long long ld_out,
                 long long sIn, long long sOut)
{
    in  += (long long)blockIdx.z * sIn;
    out += (long long)blockIdx.z * sOut;
    __shared__ float tile[32][33];
    const int rb = blockIdx.y * 32;
    const int cb = blockIdx.x * 32;
    const int tx = threadIdx.x & 31;
    const int ty = threadIdx.x >> 5;
    #pragma unroll
    for (int i = 0; i < 4; i++)
        tile[ty + i * 8][tx] = in[(long long)(rb + ty + i * 8) * ld_in + cb + tx];
    __syncthreads();
    #pragma unroll
    for (int i = 0; i < 4; i++)
        out[(long long)(cb + ty + i * 8) * ld_out + rb + tx] = tile[tx][ty + i * 8];
}

// ============================================================================
// Row softmax over 2048-wide rows.
// ============================================================================
__global__ __launch_bounds__(256)
void softmax2048(float* __restrict__ S)
{
    float* row = S + (size_t)blockIdx.x * SEQ;
    const int tid = threadIdx.x;

    float vals[8];
    float m = -1e30f;
    #pragma unroll
    for (int i = 0; i < 8; i++) {
        vals[i] = row[tid + i * 256];
        m = fmaxf(m, vals[i]);
    }

    __shared__ float rmax[8];
    __shared__ float rsum[8];

    #pragma unroll
    for (int o = 16; o; o >>= 1) m = fmaxf(m, __shfl_xor_sync(0xffffffffu, m, o));
    if ((tid & 31) == 0) rmax[tid >> 5] = m;
    __syncthreads();
    m = rmax[0];
    #pragma unroll
    for (int w = 1; w < 8; w++) m = fmaxf(m, rmax[w]);

    float s = 0.f;
    #pragma unroll
    for (int i = 0; i < 8; i++) {
        vals[i] = __expf(vals[i] - m);
        s += vals[i];
    }
    #pragma unroll
    for (int o = 16; o; o >>= 1) s += __shfl_xor_sync(0xffffffffu, s, o);
    if ((tid & 31) == 0) rsum[tid >> 5] = s;
    __syncthreads();
    s = rsum[0];
    #pragma unroll
    for (int w = 1; w < 8; w++) s += rsum[w];

    float inv = 1.f / s;
    #pragma unroll
    for (int i = 0; i < 8; i++) row[tid + i * 256] = vals[i] * inv;
}

// ============================================================================
// Highway recurrence with per-warp cp.async ring buffer (depth 16).
// ============================================================================
#define RDEPTH 16

__global__ __launch_bounds__(256)
void sru_recur2(const float* __restrict__ U, const float* __restrict__ x,
                const float* __restrict__ v, const float* __restrict__ bias,
                float* __restrict__ h)
{
    extern __shared__ float rbuf[];   // [8 warps][RDEPTH][4][32]
    const int tid  = threadIdx.x;
    const int lane = tid & 31;
    const int warp = tid >> 5;

    const int ch  = blockIdx.x * 256 + tid;
    const int b   = ch / DM;
    const int d   = ch % DM;
    const int d0w = (blockIdx.x * 256 + warp * 32) % DM;

    const int arr = lane >> 3;
    const int c4  = (lane & 7) * 4;
    const float* src;
    long long stride;
    if (arr < 3) {
        src = U + (long long)b * 3 * DM + (long long)arr * DM + d0w + c4;
        stride = (long long)NB * 3 * DM;
    } else {
        src = x + (long long)b * DM + d0w + c4;
        stride = (long long)NB * DM;
    }

    const uint32_t wbase = (uint32_t)__cvta_generic_to_shared(rbuf) + warp * RDEPTH * 512;

    #pragma unroll
    for (int s = 0; s < RDEPTH; s++) {
        cp16(wbase + s * 512 + lane * 16, src);
        src += stride;
        cp_commit();
    }

    const float vf = v[d],    vr = v[DM + d];
    const float bf = bias[d], br = bias[DM + d];
    float c = 0.f;
    float* hp = h + (long long)b * DM + d;
    const long long hstride = (long long)NB * DM;
    const float* warp_smem = rbuf + warp * RDEPTH * 128;

    for (int l = 0; l < SEQ; l++) {
        const int st = l & (RDEPTH - 1);
        asm volatile("cp.async.wait_group %0;" :: "n"(RDEPTH - 1));
        __syncwarp();
        float xt   = warp_smem[st * 128 + 0 * 32 + lane];
        float fr   = warp_smem[st * 128 + 1 * 32 + lane];
        float rr   = warp_smem[st * 128 + 2 * 32 + lane];
        float xres = warp_smem[st * 128 + 3 * 32 + lane];
        __syncwarp();
        if (l + RDEPTH < SEQ) { cp16(wbase + st * 512 + lane * 16, src); src += stride; }
        cp_commit();

        float f = 1.f / (1.f + __expf(-(fr + vf * c + bf)));
        float r = 1.f / (1.f + __expf(-(rr + vr * c + br)));
        c = f * c + (1.f - f) * xt;
        hp[0] = r * c + (1.f - r) * xres;
        hp += hstride;
    }
}

// ============================================================================
// Launch
// ============================================================================
extern "C" void kernel_launch(void* const* d_in, const int* in_sizes, int n_in,
                              void* d_out, int out_size)
{
    const float* x  = (const float*)d_in[0];
    const float* W1 = (const float*)d_in[1];
    const float* W2 = (const float*)d_in[2];
    const float* W3 = (const float*)d_in[3];
    const float* v  = (const float*)d_in[4];
    const float* bb = (const float*)d_in[5];
    float* h = (float*)d_out;

    float *q, *kv, *sc, *cq, *U, *vaT, *W1T, *W2T, *W3T;
    cudaGetSymbolAddress((void**)&q,   g_q);
    cudaGetSymbolAddress((void**)&kv,  g_kv);
    cudaGetSymbolAddress((void**)&sc,  g_scores);
    cudaGetSymbolAddress((void**)&cq,  g_cq);
    cudaGetSymbolAddress((void**)&U,   g_U);
    cudaGetSymbolAddress((void**)&vaT, g_vaT);
    cudaGetSymbolAddress((void**)&W1T, g_W1T);
    cudaGetSymbolAddress((void**)&W2T, g_W2T);
    cudaGetSymbolAddress((void**)&W3T, g_W3T);

    const int smem_bytes = STAGES * 2 * TILE_BYTES;        // 96KB
    const int rec_smem   = 8 * RDEPTH * 4 * 32 * 4;        // 64KB
    cudaFuncSetAttribute(gemm_tn<false>, cudaFuncAttributeMaxDynamicSharedMemorySize, smem_bytes);
    cudaFuncSetAttribute(gemm_tn<true>,  cudaFuncAttributeMaxDynamicSharedMemorySize, smem_bytes);
    cudaFuncSetAttribute(sru_recur2,     cudaFuncAttributeMaxDynamicSharedMemorySize, rec_smem);

    const dim3 T(128);
    const float scale = 1.0f / sqrtf((float)DH);

    transpose_k<<<dim3(DH / 32, DM / 32, 1), 256>>>(W1, W1T, DM, DH, DH, DM, 0, 0);
    transpose_k<<<dim3(DM / 32, DH / 32, 1), 256>>>(W2, W2T, DH, DM, DM, DH, 0, 0);
    transpose_k<<<dim3(3 * DM / 32, DH / 32, 1), 256>>>(W3, W3T, DH, 3 * DM, 3 * DM, DH, 0, 0);

    gemm_tn<false><<<dim3(DH / 128, ROWS / 128, 1), T, smem_bytes>>>(
        x, W1T, q, nullptr, DM, DM, DM, DH, 0, 1.f, 0, 0, 0, 0);

    gemm_tn<false><<<dim3(2 * DH / 128, ROWS / 128, 1), T, smem_bytes>>>(
        q, W2T, kv, nullptr, DH, DH, DH, 2 * DH, 0, 1.f, 0, 0, 0, 0);

    gemm_tn<false><<<dim3(SEQ / 128, SEQ / 128, NB), T, smem_bytes>>>(
        q, kv, sc, nullptr, DH, NB * DH, NB * 2 * DH, SEQ, 0, scale,
        (long long)DH, (long long)(2 * DH), (long long)SEQ * SEQ, 0);

    softmax2048<<<NB * SEQ, 256>>>(sc);

    transpose_k<<<dim3(DH / 32, SEQ / 32, NB), 256>>>(
        kv + DH, vaT, SEQ, DH, (long long)NB * 2 * DH, SEQ,
        (long long)(2 * DH), (long long)DH * SEQ);

    gemm_tn<true><<<dim3(DH / 128, SEQ / 128, NB), T, smem_bytes>>>(
        sc, vaT, cq, q, SEQ, SEQ, SEQ, NB * DH, NB * DH, 1.f,
        (long long)SEQ * SEQ, (long long)DH * SEQ, (long long)DH, (long long)DH);

    gemm_tn<false><<<dim3(3 * DM / 128, ROWS / 128, 1), T, smem_bytes>>>(
        cq, W3T, U, nullptr, DH, DH, DH, 3 * DM, 0, 1.f, 0, 0, 0, 0);

    sru_recur2<<<(NB * DM) / 256, 256, rec_smem>>>(U, x, v, bb, h);
}

// round 7
// speedup vs baseline: 8.6744x; 1.3491x over previous
#include <cuda_runtime.h>
#include <cuda_fp16.h>
#include <math.h>
#include <stdint.h>

#define SEQ 2048
#define NB  16
#define DM  1024
#define DH  512

static constexpr size_t ROWS = (size_t)SEQ * NB;   // 32768

// ---- scratch (device globals; no allocation allowed) ----
__device__ float  g_q[ROWS * DH];                    //  64 MB (fp32, needed for ctx add)
__device__ float  g_scores[(size_t)NB * SEQ * SEQ];  // 256 MB
__device__ float  g_U[ROWS * 3 * DM];                // 384 MB
__device__ __half g_xh[ROWS * DM];                   //  64 MB
__device__ __half g_qh[ROWS * DH];                   //  32 MB
__device__ __half g_kvh[ROWS * 2 * DH];              //  64 MB
__device__ __half g_attnh[(size_t)NB * SEQ * SEQ];   // 128 MB
__device__ __half g_vaTh[(size_t)NB * DH * SEQ];     //  32 MB
__device__ __half g_cqh[ROWS * DH];                  //  32 MB
__device__ __half g_W1Th[DH * DM];
__device__ __half g_W2Th[DM * DH];
__device__ __half g_W3Th[3 * DM * DH];

// ============================================================================
// helpers
// ============================================================================
__device__ __forceinline__ void mma_f16(float* c, const uint32_t* a, const uint32_t* b) {
    asm volatile(
        "mma.sync.aligned.m16n8k16.row.col.f32.f16.f16.f32 "
        "{%0,%1,%2,%3}, {%4,%5,%6,%7}, {%8,%9}, {%0,%1,%2,%3};"
        : "+f"(c[0]), "+f"(c[1]), "+f"(c[2]), "+f"(c[3])
        : "r"(a[0]), "r"(a[1]), "r"(a[2]), "r"(a[3]), "r"(b[0]), "r"(b[1]));
}

__device__ __forceinline__ void ldsm_x4(uint32_t& r0, uint32_t& r1, uint32_t& r2,
                                        uint32_t& r3, uint32_t addr) {
    asm volatile("ldmatrix.sync.aligned.m8n8.x4.shared.b16 {%0,%1,%2,%3}, [%4];"
                 : "=r"(r0), "=r"(r1), "=r"(r2), "=r"(r3) : "r"(addr));
}

__device__ __forceinline__ void cp16(uint32_t smem, const void* g) {
    asm volatile("cp.async.cg.shared.global [%0], [%1], 16;" :: "r"(smem), "l"(g));
}
__device__ __forceinline__ void cp_commit() { asm volatile("cp.async.commit_group;"); }
__device__ __forceinline__ void cp_wait1()  { asm volatile("cp.async.wait_group 1;"); }

// ============================================================================
// FP16 TN GEMM (fp32 accumulate): C = alpha * A @ B^T (+ Ad), batch = grid.z.
// A: [M,K] half row-major. B: [N,K] half row-major.
// Block tile 128x128x64, 128 threads, warps 2x2 (64x64 per warp).
// 3-stage cp.async; SMEM rows = 64 halves = 128B, SW128 xor swizzle; ldmatrix
// b16 x4 fragments double-buffered across the 4 k16 slices. 2 CTAs/SM.
// Outputs: WF32 -> C (float), WF16 -> Ch (half); either or both.
// ============================================================================
#define STAGES 3
#define BKH 64
#define TILE_BYTES (128 * BKH * 2)   // 16 KB per operand per stage

template<bool ADD, bool WF32, bool WF16>
__global__ __launch_bounds__(128, 2)
void gemm_h(const __half* __restrict__ A, const __half* __restrict__ B,
            float* __restrict__ C, __half* __restrict__ Ch,
            const float* __restrict__ Ad,
            int K, int lda, int ldb, int ldc, int ldch, int ldad, float alpha,
            long long sA, long long sB, long long sC, long long sCh, long long sAd)
{
    A += (long long)blockIdx.z * sA;
    B += (long long)blockIdx.z * sB;
    if (WF32) C  += (long long)blockIdx.z * sC;
    if (WF16) Ch += (long long)blockIdx.z * sCh;
    if (ADD)  Ad += (long long)blockIdx.z * sAd;

    extern __shared__ char smem[];
    const uint32_t smem_u32 = (uint32_t)__cvta_generic_to_shared(smem);
    const uint32_t a_base = smem_u32;
    const uint32_t b_base = smem_u32 + STAGES * TILE_BYTES;

    const int m0 = blockIdx.y * 128;
    const int n0 = blockIdx.x * 128;
    const int tid  = threadIdx.x;
    const int lane = tid & 31;
    const int warp = tid >> 5;
    const int wm = (warp >> 1) * 64;
    const int wn = (warp & 1) * 64;

    // ---- loader: 128 rows x 8 chunks(16B = 8 halves), 8 per thread per tile ----
    int lrow[8], lchk[8];
    uint32_t lsw[8];
    #pragma unroll
    for (int i = 0; i < 8; i++) {
        int id = i * 128 + tid;
        lrow[i] = id >> 3;
        lchk[i] = id & 7;
        lsw[i]  = (uint32_t)(lrow[i] * 128 + ((lchk[i] ^ (lrow[i] & 7)) << 4));
    }

    auto issue = [&](int kt, int buf) {
        const uint32_t ab = a_base + buf * TILE_BYTES;
        const uint32_t bb = b_base + buf * TILE_BYTES;
        const int k0 = kt * BKH;
        #pragma unroll
        for (int i = 0; i < 8; i++)
            cp16(ab + lsw[i], A + (long long)(m0 + lrow[i]) * lda + k0 + lchk[i] * 8);
        #pragma unroll
        for (int i = 0; i < 8; i++)
            cp16(bb + lsw[i], B + (long long)(n0 + lrow[i]) * ldb + k0 + lchk[i] * 8);
    };

    // ---- ldmatrix lane geometry (validated mapping from tf32 A-operand) ----
    // lanes 0-7:(lo rows,c0) 8-15:(hi rows,c0) 16-23:(lo,c1) 24-31:(hi,c1)
    const int mi = lane >> 3;
    const int lr = lane & 7;
    const int row16 = (mi & 1) * 8 + lr;   // row within 16-row group
    const int cadd  = mi >> 1;             // 16B chunk select within k16

    float acc[4][8][4];
    #pragma unroll
    for (int mt = 0; mt < 4; mt++)
        #pragma unroll
        for (int nt = 0; nt < 8; nt++)
            #pragma unroll
            for (int r = 0; r < 4; r++) acc[mt][nt][r] = 0.f;

    uint32_t af[2][4][4], bf[2][8][2];

    auto load_frags = [&](uint32_t ab, uint32_t bb, int s, int pb) {
        const int c = 2 * s + cadd;   // chunk pair base for k16 slice s
        #pragma unroll
        for (int mt = 0; mt < 4; mt++) {
            int m = wm + mt * 16 + row16;
            ldsm_x4(af[pb][mt][0], af[pb][mt][1], af[pb][mt][2], af[pb][mt][3],
                    ab + m * 128 + ((c ^ (m & 7)) << 4));
        }
        #pragma unroll
        for (int np = 0; np < 4; np++) {
            int n = wn + np * 16 + row16;
            uint32_t r0, r1, r2, r3;
            ldsm_x4(r0, r1, r2, r3, bb + n * 128 + ((c ^ (n & 7)) << 4));
            // r0=(nlo,k0-7) r1=(nhi,k0-7) r2=(nlo,k8-15) r3=(nhi,k8-15)
            bf[pb][2 * np][0]     = r0; bf[pb][2 * np][1]     = r2;
            bf[pb][2 * np + 1][0] = r1; bf[pb][2 * np + 1][1] = r3;
        }
    };

    const int KT = K / BKH;
    issue(0, 0); cp_commit();
    issue(1, 1); cp_commit();

    for (int kt = 0; kt < KT; kt++) {
        const int buf = kt % STAGES;
        cp_wait1();
        __syncthreads();

        if (kt + 2 < KT) issue(kt + 2, (kt + 2) % STAGES);
        cp_commit();

        const uint32_t ab = a_base + buf * TILE_BYTES;
        const uint32_t bb = b_base + buf * TILE_BYTES;

        load_frags(ab, bb, 0, 0);
        #pragma unroll
        for (int s = 0; s < 4; s++) {      // 4 x k16 slices = BK 64
            const int pb = s & 1;
            if (s < 3) load_frags(ab, bb, s + 1, pb ^ 1);
            #pragma unroll
            for (int mt = 0; mt < 4; mt++)
                #pragma unroll
                for (int nt = 0; nt < 8; nt++)
                    mma_f16(acc[mt][nt], af[pb][mt], bf[pb][nt]);
        }
    }

    // ---- epilogue ----
    const int g = lane >> 2;
    const int t = lane & 3;
    #pragma unroll
    for (int mt = 0; mt < 4; mt++) {
        int r0 = m0 + wm + mt * 16 + g;
        #pragma unroll
        for (int nt = 0; nt < 8; nt++) {
            int c0 = n0 + wn + nt * 8 + 2 * t;
            float* a4 = acc[mt][nt];
            float2 v0 = {alpha * a4[0], alpha * a4[1]};
            float2 v1 = {alpha * a4[2], alpha * a4[3]};
            if (ADD) {
                float2 d0 = *(const float2*)(Ad + (long long)r0 * ldad + c0);
                float2 d1 = *(const float2*)(Ad + (long long)(r0 + 8) * ldad + c0);
                v0.x += d0.x; v0.y += d0.y;
                v1.x += d1.x; v1.y += d1.y;
            }
            if (WF32) {
                *(float2*)(C + (long long)r0 * ldc + c0) = v0;
                *(float2*)(C + (long long)(r0 + 8) * ldc + c0) = v1;
            }
            if (WF16) {
                *(__half2*)(Ch + (long long)r0 * ldch + c0) = __floats2half2_rn(v0.x, v0.y);
                *(__half2*)(Ch + (long long)(r0 + 8) * ldch + c0) = __floats2half2_rn(v1.x, v1.y);
            }
        }
    }
}

// ============================================================================
// fp32 -> fp16 elementwise conversion (n multiple of 1024)
// ============================================================================
__global__ __launch_bounds__(256)
void conv_f2h(const float* __restrict__ in, __half* __restrict__ out)
{
    long long i = ((long long)blockIdx.x * 256 + threadIdx.x) * 4;
    float4 v = *(const float4*)(in + i);
    *(__half2*)(out + i)     = __floats2half2_rn(v.x, v.y);
    *(__half2*)(out + i + 2) = __floats2half2_rn(v.z, v.w);
}

// ============================================================================
// Tiled transposes (batched): float-in/half-out and half-in/half-out
// ============================================================================
__global__ __launch_bounds__(256)
void transpose_f2h(const float* __restrict__ in, __half* __restrict__ out,
                   long long ld_in, long long ld_out, long long sIn, long long sOut)
{
    in  += (long long)blockIdx.z * sIn;
    out += (long long)blockIdx.z * sOut;
    __shared__ float tile[32][33];
    const int rb = blockIdx.y * 32;
    const int cb = blockIdx.x * 32;
    const int tx = threadIdx.x & 31;
    const int ty = threadIdx.x >> 5;
    #pragma unroll
    for (int i = 0; i < 4; i++)
        tile[ty + i * 8][tx] = in[(long long)(rb + ty + i * 8) * ld_in + cb + tx];
    __syncthreads();
    #pragma unroll
    for (int i = 0; i < 4; i++)
        out[(long long)(cb + ty + i * 8) * ld_out + rb + tx] =
            __float2half(tile[tx][ty + i * 8]);
}

__global__ __launch_bounds__(256)
void transpose_h2h(const __half* __restrict__ in, __half* __restrict__ out,
                   long long ld_in, long long ld_out, long long sIn, long long sOut)
{
    in  += (long long)blockIdx.z * sIn;
    out += (long long)blockIdx.z * sOut;
    __shared__ float tile[32][33];
    const int rb = blockIdx.y * 32;
    const int cb = blockIdx.x * 32;
    const int tx = threadIdx.x & 31;
    const int ty = threadIdx.x >> 5;
    #pragma unroll
    for (int i = 0; i < 4; i++)
        tile[ty + i * 8][tx] = __half2float(in[(long long)(rb + ty + i * 8) * ld_in + cb + tx]);
    __syncthreads();
    #pragma unroll
    for (int i = 0; i < 4; i++)
        out[(long long)(cb + ty + i * 8) * ld_out + rb + tx] =
            __float2half(tile[tx][ty + i * 8]);
}

// ============================================================================
// Row softmax over 2048-wide fp32 rows, fp16 output.
// ============================================================================
__global__ __launch_bounds__(256)
void softmax2048h(const float* __restrict__ S, __half* __restrict__ O)
{
    const float* row = S + (size_t)blockIdx.x * SEQ;
    __half* orow = O + (size_t)blockIdx.x * SEQ;
    const int tid = threadIdx.x;

    float vals[8];
    float m = -1e30f;
    #pragma unroll
    for (int i = 0; i < 8; i++) {
        vals[i] = row[tid + i * 256];
        m = fmaxf(m, vals[i]);
    }

    __shared__ float rmax[8];
    __shared__ float rsum[8];

    #pragma unroll
    for (int o = 16; o; o >>= 1) m = fmaxf(m, __shfl_xor_sync(0xffffffffu, m, o));
    if ((tid & 31) == 0) rmax[tid >> 5] = m;
    __syncthreads();
    m = rmax[0];
    #pragma unroll
    for (int w = 1; w < 8; w++) m = fmaxf(m, rmax[w]);

    float s = 0.f;
    #pragma unroll
    for (int i = 0; i < 8; i++) {
        vals[i] = __expf(vals[i] - m);
        s += vals[i];
    }
    #pragma unroll
    for (int o = 16; o; o >>= 1) s += __shfl_xor_sync(0xffffffffu, s, o);
    if ((tid & 31) == 0) rsum[tid >> 5] = s;
    __syncthreads();
    s = rsum[0];
    #pragma unroll
    for (int w = 1; w < 8; w++) s += rsum[w];

    float inv = 1.f / s;
    #pragma unroll
    for (int i = 0; i < 8; i++) orow[tid + i * 256] = __float2half(vals[i] * inv);
}

// ============================================================================
// Highway recurrence with per-warp cp.async ring buffer (depth 16).
// ============================================================================
#define RDEPTH 16

__global__ __launch_bounds__(256)
void sru_recur2(const float* __restrict__ U, const float* __restrict__ x,
                const float* __restrict__ v, const float* __restrict__ bias,
                float* __restrict__ h)
{
    extern __shared__ float rbuf[];
    const int tid  = threadIdx.x;
    const int lane = tid & 31;
    const int warp = tid >> 5;

    const int ch  = blockIdx.x * 256 + tid;
    const int b   = ch / DM;
    const int d   = ch % DM;
    const int d0w = (blockIdx.x * 256 + warp * 32) % DM;

    const int arr = lane >> 3;
    const int c4  = (lane & 7) * 4;
    const float* src;
    long long stride;
    if (arr < 3) {
        src = U + (long long)b * 3 * DM + (long long)arr * DM + d0w + c4;
        stride = (long long)NB * 3 * DM;
    } else {
        src = x + (long long)b * DM + d0w + c4;
        stride = (long long)NB * DM;
    }

    const uint32_t wbase = (uint32_t)__cvta_generic_to_shared(rbuf) + warp * RDEPTH * 512;

    #pragma unroll
    for (int s = 0; s < RDEPTH; s++) {
        cp16(wbase + s * 512 + lane * 16, src);
        src += stride;
        cp_commit();
    }

    const float vf = v[d],    vr = v[DM + d];
    const float bf = bias[d], br = bias[DM + d];
    float c = 0.f;
    float* hp = h + (long long)b * DM + d;
    const long long hstride = (long long)NB * DM;
    const float* warp_smem = rbuf + warp * RDEPTH * 128;

    for (int l = 0; l < SEQ; l++) {
        const int st = l & (RDEPTH - 1);
        asm volatile("cp.async.wait_group %0;" :: "n"(RDEPTH - 1));
        __syncwarp();
        float xt   = warp_smem[st * 128 + 0 * 32 + lane];
        float fr   = warp_smem[st * 128 + 1 * 32 + lane];
        float rr   = warp_smem[st * 128 + 2 * 32 + lane];
        float xres = warp_smem[st * 128 + 3 * 32 + lane];
        __syncwarp();
        if (l + RDEPTH < SEQ) { cp16(wbase + st * 512 + lane * 16, src); src += stride; }
        cp_commit();

        float f = 1.f / (1.f + __expf(-(fr + vf * c + bf)));
        float r = 1.f / (1.f + __expf(-(rr + vr * c + br)));
        c = f * c + (1.f - f) * xt;
        hp[0] = r * c + (1.f - r) * xres;
        hp += hstride;
    }
}

// ============================================================================
// Launch
// ============================================================================
extern "C" void kernel_launch(void* const* d_in, const int* in_sizes, int n_in,
                              void* d_out, int out_size)
{
    const float* x  = (const float*)d_in[0];
    const float* W1 = (const float*)d_in[1];   // [1024,512]
    const float* W2 = (const float*)d_in[2];   // [512,1024]
    const float* W3 = (const float*)d_in[3];   // [512,3072]
    const float* v  = (const float*)d_in[4];
    const float* bb = (const float*)d_in[5];
    float* h = (float*)d_out;

    float *q, *sc, *U;
    __half *xh, *qh, *kvh, *attnh, *vaTh, *cqh, *W1Th, *W2Th, *W3Th;
    cudaGetSymbolAddress((void**)&q,     g_q);
    cudaGetSymbolAddress((void**)&sc,    g_scores);
    cudaGetSymbolAddress((void**)&U,     g_U);
    cudaGetSymbolAddress((void**)&xh,    g_xh);
    cudaGetSymbolAddress((void**)&qh,    g_qh);
    cudaGetSymbolAddress((void**)&kvh,   g_kvh);
    cudaGetSymbolAddress((void**)&attnh, g_attnh);
    cudaGetSymbolAddress((void**)&vaTh,  g_vaTh);
    cudaGetSymbolAddress((void**)&cqh,   g_cqh);
    cudaGetSymbolAddress((void**)&W1Th,  g_W1Th);
    cudaGetSymbolAddress((void**)&W2Th,  g_W2Th);
    cudaGetSymbolAddress((void**)&W3Th,  g_W3Th);

    const int smem_bytes = STAGES * 2 * TILE_BYTES;   // 96 KB
    const int rec_smem   = 8 * RDEPTH * 4 * 32 * 4;   // 64 KB
    cudaFuncSetAttribute((const void*)gemm_h<false, true,  true >, cudaFuncAttributeMaxDynamicSharedMemorySize, smem_bytes);
    cudaFuncSetAttribute((const void*)gemm_h<false, false, true >, cudaFuncAttributeMaxDynamicSharedMemorySize, smem_bytes);
    cudaFuncSetAttribute((const void*)gemm_h<false, true,  false>, cudaFuncAttributeMaxDynamicSharedMemorySize, smem_bytes);
    cudaFuncSetAttribute((const void*)gemm_h<true,  false, true >, cudaFuncAttributeMaxDynamicSharedMemorySize, smem_bytes);
    cudaFuncSetAttribute((const void*)sru_recur2, cudaFuncAttributeMaxDynamicSharedMemorySize, rec_smem);

    const dim3 T(128);
    const float scale = 1.0f / sqrtf((float)DH);

    // operand prep
    conv_f2h<<<(int)(ROWS * DM / 1024), 256>>>(x, xh);
    transpose_f2h<<<dim3(DH / 32, DM / 32, 1), 256>>>(W1, W1Th, DH, DM, 0, 0);
    transpose_f2h<<<dim3(DM / 32, DH / 32, 1), 256>>>(W2, W2Th, DM, DH, 0, 0);
    transpose_f2h<<<dim3(3 * DM / 32, DH / 32, 1), 256>>>(W3, W3Th, 3 * DM, DH, 0, 0);

    // q = x @ W1 -> q (f32) + qh (f16)
    gemm_h<false, true, true><<<dim3(DH / 128, ROWS / 128, 1), T, smem_bytes>>>(
        xh, W1Th, q, qh, nullptr, DM, DM, DM, DH, DH, 0, 1.f, 0, 0, 0, 0, 0);

    // kv = q @ W2 -> kvh (f16 only)
    gemm_h<false, false, true><<<dim3(2 * DH / 128, ROWS / 128, 1), T, smem_bytes>>>(
        qh, W2Th, nullptr, kvh, nullptr, DH, DH, DH, 0, 2 * DH, 0, 1.f, 0, 0, 0, 0, 0);

    // scores[b] = scale * Q_b @ K_b^T -> sc (f32)
    gemm_h<false, true, false><<<dim3(SEQ / 128, SEQ / 128, NB), T, smem_bytes>>>(
        qh, kvh, sc, nullptr, nullptr, DH, NB * DH, NB * 2 * DH, SEQ, 0, 0, scale,
        (long long)DH, (long long)(2 * DH), (long long)SEQ * SEQ, 0, 0);

    // softmax -> attnh (f16)
    softmax2048h<<<NB * SEQ, 256>>>(sc, attnh);

    // vaT[b][p][l] = kvh[l][b][DH + p]  (f16 -> f16)
    transpose_h2h<<<dim3(DH / 32, SEQ / 32, NB), 256>>>(
        kvh + DH, vaTh, (long long)NB * 2 * DH, SEQ,
        (long long)(2 * DH), (long long)DH * SEQ);

    // cq[b] = attn_b @ vaT_b^T + Q_b -> cqh (f16 only)
    gemm_h<true, false, true><<<dim3(DH / 128, SEQ / 128, NB), T, smem_bytes>>>(
        attnh, vaTh, nullptr, cqh, q, SEQ, SEQ, SEQ, 0, NB * DH, NB * DH, 1.f,
        (long long)SEQ * SEQ, (long long)DH * SEQ, 0, (long long)DH, (long long)DH);

    // U = cq @ W3 -> U (f32)
    gemm_h<false, true, false><<<dim3(3 * DM / 128, ROWS / 128, 1), T, smem_bytes>>>(
        cqh, W3Th, U, nullptr, nullptr, DH, DH, DH, 3 * DM, 0, 0, 1.f, 0, 0, 0, 0, 0);

    // elementwise highway recurrence over time
    sru_recur2<<<(NB * DM) / 256, 256, rec_smem>>>(U, x, v, bb, h);
}

// round 8
// speedup vs baseline: 8.7663x; 1.0106x over previous
#include <cuda_runtime.h>
#include <cuda_fp16.h>
#include <math.h>
#include <stdint.h>

#define SEQ 2048
#define NB  16
#define DM  1024
#define DH  512

static constexpr size_t ROWS = (size_t)SEQ * NB;   // 32768

// ---- scratch (device globals; no allocation allowed) ----
__device__ __half g_xh[ROWS * DM];                   //  64 MB
__device__ __half g_qh[ROWS * DH];                   //  32 MB
__device__ __half g_kvh[ROWS * 2 * DH];              //  64 MB
__device__ __half g_attnh[(size_t)NB * SEQ * SEQ];   // 128 MB (scores, softmaxed in place)
__device__ __half g_vaTh[(size_t)NB * DH * SEQ];     //  32 MB
__device__ __half g_cqh[ROWS * DH];                  //  32 MB
__device__ __half g_Uh[ROWS * 3 * DM];               // 192 MB
__device__ __half g_W1Th[DH * DM];
__device__ __half g_W2Th[DM * DH];
__device__ __half g_W3Th[3 * DM * DH];

// ============================================================================
// helpers
// ============================================================================
__device__ __forceinline__ void mma_f16(float* c, const uint32_t* a, const uint32_t* b) {
    asm volatile(
        "mma.sync.aligned.m16n8k16.row.col.f32.f16.f16.f32 "
        "{%0,%1,%2,%3}, {%4,%5,%6,%7}, {%8,%9}, {%0,%1,%2,%3};"
        : "+f"(c[0]), "+f"(c[1]), "+f"(c[2]), "+f"(c[3])
        : "r"(a[0]), "r"(a[1]), "r"(a[2]), "r"(a[3]), "r"(b[0]), "r"(b[1]));
}

__device__ __forceinline__ void ldsm_x4(uint32_t& r0, uint32_t& r1, uint32_t& r2,
                                        uint32_t& r3, uint32_t addr) {
    asm volatile("ldmatrix.sync.aligned.m8n8.x4.shared.b16 {%0,%1,%2,%3}, [%4];"
                 : "=r"(r0), "=r"(r1), "=r"(r2), "=r"(r3) : "r"(addr));
}

__device__ __forceinline__ void cp16(uint32_t smem, const void* g) {
    asm volatile("cp.async.cg.shared.global [%0], [%1], 16;" :: "r"(smem), "l"(g));
}
__device__ __forceinline__ void cp_commit() { asm volatile("cp.async.commit_group;"); }
__device__ __forceinline__ void cp_wait1()  { asm volatile("cp.async.wait_group 1;"); }

// ============================================================================
// FP16 TN GEMM (fp32 accumulate): C = alpha * A @ B^T (+ Ad), batch = grid.z.
// A: [M,K] half. B: [N,K] half. Outputs: WF32 -> C (float), WF16 -> Ch (half).
// Ad (residual) is HALF. Block tile 128x128x64, 128 threads, 2x2 warps.
// 3-stage cp.async, SW128 xor swizzle, b16 ldmatrix.x4, 2 CTAs/SM.
// ============================================================================
#define STAGES 3
#define BKH 64
#define TILE_BYTES (128 * BKH * 2)   // 16 KB per operand per stage

template<bool ADD, bool WF32, bool WF16>
__global__ __launch_bounds__(128, 2)
void gemm_h(const __half* __restrict__ A, const __half* __restrict__ B,
            float* __restrict__ C, __half* __restrict__ Ch,
            const __half* __restrict__ Ad,
            int K, int lda, int ldb, int ldc, int ldch, int ldad, float alpha,
            long long sA, long long sB, long long sC, long long sCh, long long sAd)
{
    A += (long long)blockIdx.z * sA;
    B += (long long)blockIdx.z * sB;
    if (WF32) C  += (long long)blockIdx.z * sC;
    if (WF16) Ch += (long long)blockIdx.z * sCh;
    if (ADD)  Ad += (long long)blockIdx.z * sAd;

    extern __shared__ char smem[];
    const uint32_t smem_u32 = (uint32_t)__cvta_generic_to_shared(smem);
    const uint32_t a_base = smem_u32;
    const uint32_t b_base = smem_u32 + STAGES * TILE_BYTES;

    const int m0 = blockIdx.y * 128;
    const int n0 = blockIdx.x * 128;
    const int tid  = threadIdx.x;
    const int lane = tid & 31;
    const int warp = tid >> 5;
    const int wm = (warp >> 1) * 64;
    const int wn = (warp & 1) * 64;

    int lrow[8], lchk[8];
    uint32_t lsw[8];
    #pragma unroll
    for (int i = 0; i < 8; i++) {
        int id = i * 128 + tid;
        lrow[i] = id >> 3;
        lchk[i] = id & 7;
        lsw[i]  = (uint32_t)(lrow[i] * 128 + ((lchk[i] ^ (lrow[i] & 7)) << 4));
    }

    auto issue = [&](int kt, int buf) {
        const uint32_t ab = a_base + buf * TILE_BYTES;
        const uint32_t bb = b_base + buf * TILE_BYTES;
        const int k0 = kt * BKH;
        #pragma unroll
        for (int i = 0; i < 8; i++)
            cp16(ab + lsw[i], A + (long long)(m0 + lrow[i]) * lda + k0 + lchk[i] * 8);
        #pragma unroll
        for (int i = 0; i < 8; i++)
            cp16(bb + lsw[i], B + (long long)(n0 + lrow[i]) * ldb + k0 + lchk[i] * 8);
    };

    const int mi = lane >> 3;
    const int lr = lane & 7;
    const int row16 = (mi & 1) * 8 + lr;
    const int cadd  = mi >> 1;

    float acc[4][8][4];
    #pragma unroll
    for (int mt = 0; mt < 4; mt++)
        #pragma unroll
        for (int nt = 0; nt < 8; nt++)
            #pragma unroll
            for (int r = 0; r < 4; r++) acc[mt][nt][r] = 0.f;

    uint32_t af[2][4][4], bf[2][8][2];

    auto load_frags = [&](uint32_t ab, uint32_t bb, int s, int pb) {
        const int c = 2 * s + cadd;
        #pragma unroll
        for (int mt = 0; mt < 4; mt++) {
            int m = wm + mt * 16 + row16;
            ldsm_x4(af[pb][mt][0], af[pb][mt][1], af[pb][mt][2], af[pb][mt][3],
                    ab + m * 128 + ((c ^ (m & 7)) << 4));
        }
        #pragma unroll
        for (int np = 0; np < 4; np++) {
            int n = wn + np * 16 + row16;
            uint32_t r0, r1, r2, r3;
            ldsm_x4(r0, r1, r2, r3, bb + n * 128 + ((c ^ (n & 7)) << 4));
            bf[pb][2 * np][0]     = r0; bf[pb][2 * np][1]     = r2;
            bf[pb][2 * np + 1][0] = r1; bf[pb][2 * np + 1][1] = r3;
        }
    };

    const int KT = K / BKH;
    issue(0, 0); cp_commit();
    issue(1, 1); cp_commit();

    for (int kt = 0; kt < KT; kt++) {
        const int buf = kt % STAGES;
        cp_wait1();
        __syncthreads();

        if (kt + 2 < KT) issue(kt + 2, (kt + 2) % STAGES);
        cp_commit();

        const uint32_t ab = a_base + buf * TILE_BYTES;
        const uint32_t bb = b_base + buf * TILE_BYTES;

        load_frags(ab, bb, 0, 0);
        #pragma unroll
        for (int s = 0; s < 4; s++) {
            const int pb = s & 1;
            if (s < 3) load_frags(ab, bb, s + 1, pb ^ 1);
            #pragma unroll
            for (int mt = 0; mt < 4; mt++)
                #pragma unroll
                for (int nt = 0; nt < 8; nt++)
                    mma_f16(acc[mt][nt], af[pb][mt], bf[pb][nt]);
        }
    }

    const int g = lane >> 2;
    const int t = lane & 3;
    #pragma unroll
    for (int mt = 0; mt < 4; mt++) {
        int r0 = m0 + wm + mt * 16 + g;
        #pragma unroll
        for (int nt = 0; nt < 8; nt++) {
            int c0 = n0 + wn + nt * 8 + 2 * t;
            float* a4 = acc[mt][nt];
            float2 v0 = {alpha * a4[0], alpha * a4[1]};
            float2 v1 = {alpha * a4[2], alpha * a4[3]};
            if (ADD) {
                float2 d0 = __half22float2(*(const __half2*)(Ad + (long long)r0 * ldad + c0));
                float2 d1 = __half22float2(*(const __half2*)(Ad + (long long)(r0 + 8) * ldad + c0));
                v0.x += d0.x; v0.y += d0.y;
                v1.x += d1.x; v1.y += d1.y;
            }
            if (WF32) {
                *(float2*)(C + (long long)r0 * ldc + c0) = v0;
                *(float2*)(C + (long long)(r0 + 8) * ldc + c0) = v1;
            }
            if (WF16) {
                *(__half2*)(Ch + (long long)r0 * ldch + c0) = __floats2half2_rn(v0.x, v0.y);
                *(__half2*)(Ch + (long long)(r0 + 8) * ldch + c0) = __floats2half2_rn(v1.x, v1.y);
            }
        }
    }
}

// ============================================================================
// fp32 -> fp16 elementwise conversion (n multiple of 1024)
// ============================================================================
__global__ __launch_bounds__(256)
void conv_f2h(const float* __restrict__ in, __half* __restrict__ out)
{
    long long i = ((long long)blockIdx.x * 256 + threadIdx.x) * 4;
    float4 v = *(const float4*)(in + i);
    *(__half2*)(out + i)     = __floats2half2_rn(v.x, v.y);
    *(__half2*)(out + i + 2) = __floats2half2_rn(v.z, v.w);
}

// ============================================================================
// Tiled transposes (batched)
// ============================================================================
__global__ __launch_bounds__(256)
void transpose_f2h(const float* __restrict__ in, __half* __restrict__ out,
                   long long ld_in, long long ld_out, long long sIn, long long sOut)
{
    in  += (long long)blockIdx.z * sIn;
    out += (long long)blockIdx.z * sOut;
    __shared__ float tile[32][33];
    const int rb = blockIdx.y * 32;
    const int cb = blockIdx.x * 32;
    const int tx = threadIdx.x & 31;
    const int ty = threadIdx.x >> 5;
    #pragma unroll
    for (int i = 0; i < 4; i++)
        tile[ty + i * 8][tx] = in[(long long)(rb + ty + i * 8) * ld_in + cb + tx];
    __syncthreads();
    #pragma unroll
    for (int i = 0; i < 4; i++)
        out[(long long)(cb + ty + i * 8) * ld_out + rb + tx] =
            __float2half(tile[tx][ty + i * 8]);
}

__global__ __launch_bounds__(256)
void transpose_h2h(const __half* __restrict__ in, __half* __restrict__ out,
                   long long ld_in, long long ld_out, long long sIn, long long sOut)
{
    in  += (long long)blockIdx.z * sIn;
    out += (long long)blockIdx.z * sOut;
    __shared__ float tile[32][33];
    const int rb = blockIdx.y * 32;
    const int cb = blockIdx.x * 32;
    const int tx = threadIdx.x & 31;
    const int ty = threadIdx.x >> 5;
    #pragma unroll
    for (int i = 0; i < 4; i++)
        tile[ty + i * 8][tx] = __half2float(in[(long long)(rb + ty + i * 8) * ld_in + cb + tx]);
    __syncthreads();
    #pragma unroll
    for (int i = 0; i < 4; i++)
        out[(long long)(cb + ty + i * 8) * ld_out + rb + tx] =
            __float2half(tile[tx][ty + i * 8]);
}

// ============================================================================
// In-place row softmax over 2048-wide fp16 rows (fp32 math).
// ============================================================================
__global__ __launch_bounds__(256)
void softmax2048h(__half* __restrict__ S)
{
    __half* row = S + (size_t)blockIdx.x * SEQ;
    const int tid = threadIdx.x;

    float vals[8];
    float m = -1e30f;
    #pragma unroll
    for (int i = 0; i < 8; i++) {
        vals[i] = __half2float(row[tid + i * 256]);
        m = fmaxf(m, vals[i]);
    }

    __shared__ float rmax[8];
    __shared__ float rsum[8];

    #pragma unroll
    for (int o = 16; o; o >>= 1) m = fmaxf(m, __shfl_xor_sync(0xffffffffu, m, o));
    if ((tid & 31) == 0) rmax[tid >> 5] = m;
    __syncthreads();
    m = rmax[0];
    #pragma unroll
    for (int w = 1; w < 8; w++) m = fmaxf(m, rmax[w]);

    float s = 0.f;
    #pragma unroll
    for (int i = 0; i < 8; i++) {
        vals[i] = __expf(vals[i] - m);
        s += vals[i];
    }
    #pragma unroll
    for (int o = 16; o; o >>= 1) s += __shfl_xor_sync(0xffffffffu, s, o);
    if ((tid & 31) == 0) rsum[tid >> 5] = s;
    __syncthreads();
    s = rsum[0];
    #pragma unroll
    for (int w = 1; w < 8; w++) s += rsum[w];

    float inv = 1.f / s;
    #pragma unroll
    for (int i = 0; i < 8; i++) row[tid + i * 256] = __float2half(vals[i] * inv);
}

// ============================================================================
// Highway recurrence, cp.async ring buffer (depth 16), mixed dtypes:
// U (half, 3 arrays) streamed by lanes 0-11; x residual (float) by lanes 12-19.
// Per-warp stage = 192B (U half) + 128B (x float) = 320B.
// ============================================================================
#define RDEPTH 16
#define RSTRIDE 320

__global__ __launch_bounds__(256)
void sru_recur3(const __half* __restrict__ U, const float* __restrict__ x,
                const float* __restrict__ v, const float* __restrict__ bias,
                float* __restrict__ h)
{
    extern __shared__ char rbuf[];   // [8 warps][RDEPTH][320B]
    const int tid  = threadIdx.x;
    const int lane = tid & 31;
    const int warp = tid >> 5;

    const int ch  = blockIdx.x * 256 + tid;
    const int b   = ch / DM;
    const int d   = ch % DM;
    const int d0w = (blockIdx.x * 256 + warp * 32) % DM;

    // producer mapping (lanes 0..19 active)
    const char* srcb = nullptr;
    long long strideB = 0;
    uint32_t doff = 0;
    if (lane < 12) {
        int arr = lane >> 2, chk = lane & 3;         // arr 0..2, chunk 0..3 (8 halves each)
        srcb = (const char*)(U + (long long)b * 3 * DM + (long long)arr * DM + d0w + chk * 8);
        strideB = (long long)NB * 3 * DM * 2;
        doff = (uint32_t)(arr * 64 + chk * 16);
    } else if (lane < 20) {
        int chk = lane - 12;                          // chunk 0..7 (4 floats each)
        srcb = (const char*)(x + (long long)b * DM + d0w + chk * 4);
        strideB = (long long)NB * DM * 4;
        doff = (uint32_t)(192 + chk * 16);
    }

    const uint32_t wbase = (uint32_t)__cvta_generic_to_shared(rbuf) + warp * RDEPTH * RSTRIDE;

    #pragma unroll
    for (int s = 0; s < RDEPTH; s++) {
        if (lane < 20) { cp16(wbase + s * RSTRIDE + doff, srcb); srcb += strideB; }
        cp_commit();
    }

    const float vf = v[d],    vr = v[DM + d];
    const float bf = bias[d], br = bias[DM + d];
    float c = 0.f;
    float* hp = h + (long long)b * DM + d;
    const long long hstride = (long long)NB * DM;
    const char* wsm = rbuf + warp * RDEPTH * RSTRIDE;

    for (int l = 0; l < SEQ; l++) {
        const int st = l & (RDEPTH - 1);
        const char* sp = wsm + st * RSTRIDE;
        asm volatile("cp.async.wait_group %0;" :: "n"(RDEPTH - 1));
        __syncwarp();
        float xt   = __half2float(((const __half*)sp)[lane]);
        float fr   = __half2float(((const __half*)sp)[32 + lane]);
        float rr   = __half2float(((const __half*)sp)[64 + lane]);
        float xres = ((const float*)(sp + 192))[lane];
        __syncwarp();
        if (lane < 20 && l + RDEPTH < SEQ) {
            cp16(wbase + st * RSTRIDE + doff, srcb);
            srcb += strideB;
        }
        cp_commit();

        float f = 1.f / (1.f + __expf(-(fr + vf * c + bf)));
        float r = 1.f / (1.f + __expf(-(rr + vr * c + br)));
        c = f * c + (1.f - f) * xt;
        hp[0] = r * c + (1.f - r) * xres;
        hp += hstride;
    }
}

// ============================================================================
// Launch
// ============================================================================
extern "C" void kernel_launch(void* const* d_in, const int* in_sizes, int n_in,
                              void* d_out, int out_size)
{
    const float* x  = (const float*)d_in[0];
    const float* W1 = (const float*)d_in[1];   // [1024,512]
    const float* W2 = (const float*)d_in[2];   // [512,1024]
    const float* W3 = (const float*)d_in[3];   // [512,3072]
    const float* v  = (const float*)d_in[4];
    const float* bb = (const float*)d_in[5];
    float* h = (float*)d_out;

    __half *xh, *qh, *kvh, *attnh, *vaTh, *cqh, *Uh, *W1Th, *W2Th, *W3Th;
    cudaGetSymbolAddress((void**)&xh,    g_xh);
    cudaGetSymbolAddress((void**)&qh,    g_qh);
    cudaGetSymbolAddress((void**)&kvh,   g_kvh);
    cudaGetSymbolAddress((void**)&attnh, g_attnh);
    cudaGetSymbolAddress((void**)&vaTh,  g_vaTh);
    cudaGetSymbolAddress((void**)&cqh,   g_cqh);
    cudaGetSymbolAddress((void**)&Uh,    g_Uh);
    cudaGetSymbolAddress((void**)&W1Th,  g_W1Th);
    cudaGetSymbolAddress((void**)&W2Th,  g_W2Th);
    cudaGetSymbolAddress((void**)&W3Th,  g_W3Th);

    const int smem_bytes = STAGES * 2 * TILE_BYTES;   // 96 KB
    const int rec_smem   = 8 * RDEPTH * RSTRIDE;      // 40 KB
    cudaFuncSetAttribute((const void*)gemm_h<false, false, true>, cudaFuncAttributeMaxDynamicSharedMemorySize, smem_bytes);
    cudaFuncSetAttribute((const void*)gemm_h<true,  false, true>, cudaFuncAttributeMaxDynamicSharedMemorySize, smem_bytes);
    cudaFuncSetAttribute((const void*)sru_recur3, cudaFuncAttributeMaxDynamicSharedMemorySize, rec_smem);

    const dim3 T(128);
    const float scale = 1.0f / sqrtf((float)DH);

    // operand prep
    conv_f2h<<<(int)(ROWS * DM / 1024), 256>>>(x, xh);
    transpose_f2h<<<dim3(DH / 32, DM / 32, 1), 256>>>(W1, W1Th, DH, DM, 0, 0);
    transpose_f2h<<<dim3(DM / 32, DH / 32, 1), 256>>>(W2, W2Th, DM, DH, 0, 0);
    transpose_f2h<<<dim3(3 * DM / 32, DH / 32, 1), 256>>>(W3, W3Th, 3 * DM, DH, 0, 0);

    // q = x @ W1 -> qh (f16)
    gemm_h<false, false, true><<<dim3(DH / 128, ROWS / 128, 1), T, smem_bytes>>>(
        xh, W1Th, nullptr, qh, nullptr, DM, DM, DM, 0, DH, 0, 1.f, 0, 0, 0, 0, 0);

    // kv = q @ W2 -> kvh (f16)
    gemm_h<false, false, true><<<dim3(2 * DH / 128, ROWS / 128, 1), T, smem_bytes>>>(
        qh, W2Th, nullptr, kvh, nullptr, DH, DH, DH, 0, 2 * DH, 0, 1.f, 0, 0, 0, 0, 0);

    // scores[b] = scale * Q_b @ K_b^T -> attnh (f16, scaled)
    gemm_h<false, false, true><<<dim3(SEQ / 128, SEQ / 128, NB), T, smem_bytes>>>(
        qh, kvh, nullptr, attnh, nullptr, DH, NB * DH, NB * 2 * DH, 0, SEQ, 0, scale,
        (long long)DH, (long long)(2 * DH), 0, (long long)SEQ * SEQ, 0);

    // softmax in place on fp16 rows
    softmax2048h<<<NB * SEQ, 256>>>(attnh);

    // vaT[b][p][l] = kvh[l][b][DH + p]
    transpose_h2h<<<dim3(DH / 32, SEQ / 32, NB), 256>>>(
        kvh + DH, vaTh, (long long)NB * 2 * DH, SEQ,
        (long long)(2 * DH), (long long)DH * SEQ);

    // cq[b] = attn_b @ vaT_b^T + qh_b -> cqh (f16)
    gemm_h<true, false, true><<<dim3(DH / 128, SEQ / 128, NB), T, smem_bytes>>>(
        attnh, vaTh, nullptr, cqh, qh, SEQ, SEQ, SEQ, 0, NB * DH, NB * DH, 1.f,
        (long long)SEQ * SEQ, (long long)DH * SEQ, 0, (long long)DH, (long long)DH);

    // U = cq @ W3 -> Uh (f16)
    gemm_h<false, false, true><<<dim3(3 * DM / 128, ROWS / 128, 1), T, smem_bytes>>>(
        cqh, W3Th, nullptr, Uh, nullptr, DH, DH, DH, 0, 3 * DM, 0, 1.f, 0, 0, 0, 0, 0);

    // elementwise highway recurrence over time
    sru_recur3<<<(NB * DM) / 256, 256, rec_smem>>>(Uh, x, v, bb, h);
}

// round 9
// speedup vs baseline: 8.8788x; 1.0128x over previous
#include <cuda_runtime.h>
#include <cuda_fp16.h>
#include <math.h>
#include <stdint.h>

#define SEQ 2048
#define NB  16
#define DM  1024
#define DH  512

static constexpr size_t ROWS = (size_t)SEQ * NB;   // 32768

// ---- scratch (device globals; no allocation allowed) ----
__device__ __half g_xh[ROWS * DM];                   //  64 MB
__device__ __half g_qh[ROWS * DH];                   //  32 MB
__device__ __half g_kvh[ROWS * 2 * DH];              //  64 MB
__device__ __half g_attnh[(size_t)NB * SEQ * SEQ];   // 128 MB (scores, softmaxed in place)
__device__ __half g_vaTh[(size_t)NB * DH * SEQ];     //  32 MB
__device__ __half g_cqh[ROWS * DH];                  //  32 MB
__device__ __half g_Uh[ROWS * 3 * DM];               // 192 MB
__device__ __half g_W1Th[DH * DM];
__device__ __half g_W2Th[DM * DH];
__device__ __half g_W3Th[3 * DM * DH];

// ============================================================================
// helpers
// ============================================================================
__device__ __forceinline__ void mma_f16(float* c, const uint32_t* a, const uint32_t* b) {
    asm volatile(
        "mma.sync.aligned.m16n8k16.row.col.f32.f16.f16.f32 "
        "{%0,%1,%2,%3}, {%4,%5,%6,%7}, {%8,%9}, {%0,%1,%2,%3};"
        : "+f"(c[0]), "+f"(c[1]), "+f"(c[2]), "+f"(c[3])
        : "r"(a[0]), "r"(a[1]), "r"(a[2]), "r"(a[3]), "r"(b[0]), "r"(b[1]));
}

__device__ __forceinline__ void ldsm_x4(uint32_t& r0, uint32_t& r1, uint32_t& r2,
                                        uint32_t& r3, uint32_t addr) {
    asm volatile("ldmatrix.sync.aligned.m8n8.x4.shared.b16 {%0,%1,%2,%3}, [%4];"
                 : "=r"(r0), "=r"(r1), "=r"(r2), "=r"(r3) : "r"(addr));
}

__device__ __forceinline__ void cp16(uint32_t smem, const void* g) {
    asm volatile("cp.async.cg.shared.global [%0], [%1], 16;" :: "r"(smem), "l"(g));
}
__device__ __forceinline__ void cp_commit() { asm volatile("cp.async.commit_group;"); }
__device__ __forceinline__ void cp_wait1()  { asm volatile("cp.async.wait_group 1;"); }

// ============================================================================
// FP16 TN GEMM (fp32 accumulate): C = alpha * A @ B^T (+ Ad), batch = grid.z.
// Block tile 128x128x64, 128 threads, warps 2x2 (64x64), 3-stage cp.async,
// SW128 xor swizzle, b16 ldmatrix.x4, 2 CTAs/SM.  (unchanged from round 8)
// ============================================================================
#define STAGES 3
#define BKH 64
#define TILE_BYTES (128 * BKH * 2)   // 16 KB per operand per stage

template<bool ADD, bool WF16>
__global__ __launch_bounds__(128, 2)
void gemm_h(const __half* __restrict__ A, const __half* __restrict__ B,
            __half* __restrict__ Ch, const __half* __restrict__ Ad,
            int K, int lda, int ldb, int ldch, int ldad, float alpha,
            long long sA, long long sB, long long sCh, long long sAd)
{
    A += (long long)blockIdx.z * sA;
    B += (long long)blockIdx.z * sB;
    Ch += (long long)blockIdx.z * sCh;
    if (ADD) Ad += (long long)blockIdx.z * sAd;

    extern __shared__ char smem[];
    const uint32_t smem_u32 = (uint32_t)__cvta_generic_to_shared(smem);
    const uint32_t a_base = smem_u32;
    const uint32_t b_base = smem_u32 + STAGES * TILE_BYTES;

    const int m0 = blockIdx.y * 128;
    const int n0 = blockIdx.x * 128;
    const int tid  = threadIdx.x;
    const int lane = tid & 31;
    const int warp = tid >> 5;
    const int wm = (warp >> 1) * 64;
    const int wn = (warp & 1) * 64;

    int lrow[8], lchk[8];
    uint32_t lsw[8];
    #pragma unroll
    for (int i = 0; i < 8; i++) {
        int id = i * 128 + tid;
        lrow[i] = id >> 3;
        lchk[i] = id & 7;
        lsw[i]  = (uint32_t)(lrow[i] * 128 + ((lchk[i] ^ (lrow[i] & 7)) << 4));
    }

    auto issue = [&](int kt, int buf) {
        const uint32_t ab = a_base + buf * TILE_BYTES;
        const uint32_t bb = b_base + buf * TILE_BYTES;
        const int k0 = kt * BKH;
        #pragma unroll
        for (int i = 0; i < 8; i++)
            cp16(ab + lsw[i], A + (long long)(m0 + lrow[i]) * lda + k0 + lchk[i] * 8);
        #pragma unroll
        for (int i = 0; i < 8; i++)
            cp16(bb + lsw[i], B + (long long)(n0 + lrow[i]) * ldb + k0 + lchk[i] * 8);
    };

    const int mi = lane >> 3;
    const int lr = lane & 7;
    const int row16 = (mi & 1) * 8 + lr;
    const int cadd  = mi >> 1;

    float acc[4][8][4];
    #pragma unroll
    for (int mt = 0; mt < 4; mt++)
        #pragma unroll
        for (int nt = 0; nt < 8; nt++)
            #pragma unroll
            for (int r = 0; r < 4; r++) acc[mt][nt][r] = 0.f;

    uint32_t af[2][4][4], bf[2][8][2];

    auto load_frags = [&](uint32_t ab, uint32_t bb, int s, int pb) {
        const int c = 2 * s + cadd;
        #pragma unroll
        for (int mt = 0; mt < 4; mt++) {
            int m = wm + mt * 16 + row16;
            ldsm_x4(af[pb][mt][0], af[pb][mt][1], af[pb][mt][2], af[pb][mt][3],
                    ab + m * 128 + ((c ^ (m & 7)) << 4));
        }
        #pragma unroll
        for (int np = 0; np < 4; np++) {
            int n = wn + np * 16 + row16;
            uint32_t r0, r1, r2, r3;
            ldsm_x4(r0, r1, r2, r3, bb + n * 128 + ((c ^ (n & 7)) << 4));
            bf[pb][2 * np][0]     = r0; bf[pb][2 * np][1]     = r2;
            bf[pb][2 * np + 1][0] = r1; bf[pb][2 * np + 1][1] = r3;
        }
    };

    const int KT = K / BKH;
    issue(0, 0); cp_commit();
    issue(1, 1); cp_commit();

    for (int kt = 0; kt < KT; kt++) {
        const int buf = kt % STAGES;
        cp_wait1();
        __syncthreads();

        if (kt + 2 < KT) issue(kt + 2, (kt + 2) % STAGES);
        cp_commit();

        const uint32_t ab = a_base + buf * TILE_BYTES;
        const uint32_t bb = b_base + buf * TILE_BYTES;

        load_frags(ab, bb, 0, 0);
        #pragma unroll
        for (int s = 0; s < 4; s++) {
            const int pb = s & 1;
            if (s < 3) load_frags(ab, bb, s + 1, pb ^ 1);
            #pragma unroll
            for (int mt = 0; mt < 4; mt++)
                #pragma unroll
                for (int nt = 0; nt < 8; nt++)
                    mma_f16(acc[mt][nt], af[pb][mt], bf[pb][nt]);
        }
    }

    const int g = lane >> 2;
    const int t = lane & 3;
    #pragma unroll
    for (int mt = 0; mt < 4; mt++) {
        int r0 = m0 + wm + mt * 16 + g;
        #pragma unroll
        for (int nt = 0; nt < 8; nt++) {
            int c0 = n0 + wn + nt * 8 + 2 * t;
            float* a4 = acc[mt][nt];
            float2 v0 = {alpha * a4[0], alpha * a4[1]};
            float2 v1 = {alpha * a4[2], alpha * a4[3]};
            if (ADD) {
                float2 d0 = __half22float2(*(const __half2*)(Ad + (long long)r0 * ldad + c0));
                float2 d1 = __half22float2(*(const __half2*)(Ad + (long long)(r0 + 8) * ldad + c0));
                v0.x += d0.x; v0.y += d0.y;
                v1.x += d1.x; v1.y += d1.y;
            }
            if (WF16) {
                *(__half2*)(Ch + (long long)r0 * ldch + c0) = __floats2half2_rn(v0.x, v0.y);
                *(__half2*)(Ch + (long long)(r0 + 8) * ldch + c0) = __floats2half2_rn(v1.x, v1.y);
            }
        }
    }
}

// ============================================================================
// Fused prep kernel: one launch does W1/W2/W3 transposes (f32->f16) and the
// x f32->f16 conversion, partitioned over blockIdx.x.
// Jobs: [0,512) W1T tiles, [512,1024) W2T, [1024,2560) W3T, [2560,...) conv x.
// ============================================================================
__device__ __forceinline__ void tr_tile(const float* __restrict__ in,
                                        __half* __restrict__ out,
                                        int ld_in, int ld_out, int rb, int cb)
{
    __shared__ float tile[32][33];
    const int tx = threadIdx.x & 31;
    const int ty = threadIdx.x >> 5;
    #pragma unroll
    for (int i = 0; i < 4; i++)
        tile[ty + i * 8][tx] = in[(long long)(rb + ty + i * 8) * ld_in + cb + tx];
    __syncthreads();
    #pragma unroll
    for (int i = 0; i < 4; i++)
        out[(long long)(cb + ty + i * 8) * ld_out + rb + tx] =
            __float2half(tile[tx][ty + i * 8]);
}

__global__ __launch_bounds__(256)
void prep_k(const float* __restrict__ x,  __half* __restrict__ xh,
            const float* __restrict__ W1, __half* __restrict__ W1T,
            const float* __restrict__ W2, __half* __restrict__ W2T,
            const float* __restrict__ W3, __half* __restrict__ W3T)
{
    const int bid = blockIdx.x;
    if (bid < 512) {
        // W1 [1024,512] -> W1T [512,1024]; tiles 32(r) x 16(c)
        int j = bid;
        tr_tile(W1, W1T, DH, DM, (j >> 4) * 32, (j & 15) * 32);
    } else if (bid < 1024) {
        // W2 [512,1024] -> W2T [1024,512]; tiles 16(r) x 32(c)
        int j = bid - 512;
        tr_tile(W2, W2T, DM, DH, (j >> 5) * 32, (j & 31) * 32);
    } else if (bid < 2560) {
        // W3 [512,3072] -> W3T [3072,512]; tiles 16(r) x 96(c)
        int j = bid - 1024;
        tr_tile(W3, W3T, 3 * DM, DH, (j / 96) * 32, (j % 96) * 32);
    } else {
        long long i = ((long long)(bid - 2560) * 256 + threadIdx.x) * 4;
        float4 v = *(const float4*)(x + i);
        *(__half2*)(xh + i)     = __floats2half2_rn(v.x, v.y);
        *(__half2*)(xh + i + 2) = __floats2half2_rn(v.z, v.w);
    }
}

// ============================================================================
// Tiled half->half transpose (batched) — for vaT
// ============================================================================
__global__ __launch_bounds__(256)
void transpose_h2h(const __half* __restrict__ in, __half* __restrict__ out,
                   long long ld_in, long long ld_out, long long sIn, long long sOut)
{
    in  += (long long)blockIdx.z * sIn;
    out += (long long)blockIdx.z * sOut;
    __shared__ float tile[32][33];
    const int rb = blockIdx.y * 32;
    const int cb = blockIdx.x * 32;
    const int tx = threadIdx.x & 31;
    const int ty = threadIdx.x >> 5;
    #pragma unroll
    for (int i = 0; i < 4; i++)
        tile[ty + i * 8][tx] = __half2float(in[(long long)(rb + ty + i * 8) * ld_in + cb + tx]);
    __syncthreads();
    #pragma unroll
    for (int i = 0; i < 4; i++)
        out[(long long)(cb + ty + i * 8) * ld_out + rb + tx] =
            __float2half(tile[tx][ty + i * 8]);
}

// ============================================================================
// In-place row softmax over 2048-wide fp16 rows — vectorized uint4 (8 halves).
// Thread t owns halves [8t, 8t+8).
// ============================================================================
__global__ __launch_bounds__(256)
void softmax2048h(__half* __restrict__ S)
{
    __half* row = S + (size_t)blockIdx.x * SEQ;
    const int tid = threadIdx.x;

    uint4 u = *(const uint4*)(row + tid * 8);
    const __half2* h2 = (const __half2*)&u;
    float vals[8];
    #pragma unroll
    for (int i = 0; i < 4; i++) {
        float2 f = __half22float2(h2[i]);
        vals[2 * i] = f.x; vals[2 * i + 1] = f.y;
    }

    float m = -1e30f;
    #pragma unroll
    for (int i = 0; i < 8; i++) m = fmaxf(m, vals[i]);

    __shared__ float rmax[8];
    __shared__ float rsum[8];

    #pragma unroll
    for (int o = 16; o; o >>= 1) m = fmaxf(m, __shfl_xor_sync(0xffffffffu, m, o));
    if ((tid & 31) == 0) rmax[tid >> 5] = m;
    __syncthreads();
    m = rmax[0];
    #pragma unroll
    for (int w = 1; w < 8; w++) m = fmaxf(m, rmax[w]);

    float s = 0.f;
    #pragma unroll
    for (int i = 0; i < 8; i++) {
        vals[i] = __expf(vals[i] - m);
        s += vals[i];
    }
    #pragma unroll
    for (int o = 16; o; o >>= 1) s += __shfl_xor_sync(0xffffffffu, s, o);
    if ((tid & 31) == 0) rsum[tid >> 5] = s;
    __syncthreads();
    s = rsum[0];
    #pragma unroll
    for (int w = 1; w < 8; w++) s += rsum[w];

    float inv = 1.f / s;
    uint4 o4;
    __half2* oh = (__half2*)&o4;
    #pragma unroll
    for (int i = 0; i < 4; i++)
        oh[i] = __floats2half2_rn(vals[2 * i] * inv, vals[2 * i + 1] * inv);
    *(uint4*)(row + tid * 8) = o4;
}

// ============================================================================
// Highway recurrence, cp.async ring buffer (depth 16), mixed dtypes
// (unchanged from round 8).
// ============================================================================
#define RDEPTH 16
#define RSTRIDE 320

__global__ __launch_bounds__(256)
void sru_recur3(const __half* __restrict__ U, const float* __restrict__ x,
                const float* __restrict__ v, const float* __restrict__ bias,
                float* __restrict__ h)
{
    extern __shared__ char rbuf[];
    const int tid  = threadIdx.x;
    const int lane = tid & 31;
    const int warp = tid >> 5;

    const int ch  = blockIdx.x * 256 + tid;
    const int b   = ch / DM;
    const int d   = ch % DM;
    const int d0w = (blockIdx.x * 256 + warp * 32) % DM;

    const char* srcb = nullptr;
    long long strideB = 0;
    uint32_t doff = 0;
    if (lane < 12) {
        int arr = lane >> 2, chk = lane & 3;
        srcb = (const char*)(U + (long long)b * 3 * DM + (long long)arr * DM + d0w + chk * 8);
        strideB = (long long)NB * 3 * DM * 2;
        doff = (uint32_t)(arr * 64 + chk * 16);
    } else if (lane < 20) {
        int chk = lane - 12;
        srcb = (const char*)(x + (long long)b * DM + d0w + chk * 4);
        strideB = (long long)NB * DM * 4;
        doff = (uint32_t)(192 + chk * 16);
    }

    const uint32_t wbase = (uint32_t)__cvta_generic_to_shared(rbuf) + warp * RDEPTH * RSTRIDE;

    #pragma unroll
    for (int s = 0; s < RDEPTH; s++) {
        if (lane < 20) { cp16(wbase + s * RSTRIDE + doff, srcb); srcb += strideB; }
        cp_commit();
    }

    const float vf = v[d],    vr = v[DM + d];
    const float bf = bias[d], br = bias[DM + d];
    float c = 0.f;
    float* hp = h + (long long)b * DM + d;
    const long long hstride = (long long)NB * DM;
    const char* wsm = rbuf + warp * RDEPTH * RSTRIDE;

    for (int l = 0; l < SEQ; l++) {
        const int st = l & (RDEPTH - 1);
        const char* sp = wsm + st * RSTRIDE;
        asm volatile("cp.async.wait_group %0;" :: "n"(RDEPTH - 1));
        __syncwarp();
        float xt   = __half2float(((const __half*)sp)[lane]);
        float fr   = __half2float(((const __half*)sp)[32 + lane]);
        float rr   = __half2float(((const __half*)sp)[64 + lane]);
        float xres = ((const float*)(sp + 192))[lane];
        __syncwarp();
        if (lane < 20 && l + RDEPTH < SEQ) {
            cp16(wbase + st * RSTRIDE + doff, srcb);
            srcb += strideB;
        }
        cp_commit();

        float f = 1.f / (1.f + __expf(-(fr + vf * c + bf)));
        float r = 1.f / (1.f + __expf(-(rr + vr * c + br)));
        c = f * c + (1.f - f) * xt;
        hp[0] = r * c + (1.f - r) * xres;
        hp += hstride;
    }
}

// ============================================================================
// Launch
// ============================================================================
extern "C" void kernel_launch(void* const* d_in, const int* in_sizes, int n_in,
                              void* d_out, int out_size)
{
    const float* x  = (const float*)d_in[0];
    const float* W1 = (const float*)d_in[1];   // [1024,512]
    const float* W2 = (const float*)d_in[2];   // [512,1024]
    const float* W3 = (const float*)d_in[3];   // [512,3072]
    const float* v  = (const float*)d_in[4];
    const float* bb = (const float*)d_in[5];
    float* h = (float*)d_out;

    __half *xh, *qh, *kvh, *attnh, *vaTh, *cqh, *Uh, *W1Th, *W2Th, *W3Th;
    cudaGetSymbolAddress((void**)&xh,    g_xh);
    cudaGetSymbolAddress((void**)&qh,    g_qh);
    cudaGetSymbolAddress((void**)&kvh,   g_kvh);
    cudaGetSymbolAddress((void**)&attnh, g_attnh);
    cudaGetSymbolAddress((void**)&vaTh,  g_vaTh);
    cudaGetSymbolAddress((void**)&cqh,   g_cqh);
    cudaGetSymbolAddress((void**)&Uh,    g_Uh);
    cudaGetSymbolAddress((void**)&W1Th,  g_W1Th);
    cudaGetSymbolAddress((void**)&W2Th,  g_W2Th);
    cudaGetSymbolAddress((void**)&W3Th,  g_W3Th);

    const int smem_bytes = STAGES * 2 * TILE_BYTES;   // 96 KB
    const int rec_smem   = 8 * RDEPTH * RSTRIDE;      // 40 KB
    cudaFuncSetAttribute((const void*)gemm_h<false, true>, cudaFuncAttributeMaxDynamicSharedMemorySize, smem_bytes);
    cudaFuncSetAttribute((const void*)gemm_h<true,  true>, cudaFuncAttributeMaxDynamicSharedMemorySize, smem_bytes);
    cudaFuncSetAttribute((const void*)sru_recur3, cudaFuncAttributeMaxDynamicSharedMemorySize, rec_smem);

    const dim3 T(128);
    const float scale = 1.0f / sqrtf((float)DH);

    // fused prep: W1T/W2T/W3T transposes + x conversion, one launch
    prep_k<<<2560 + (int)(ROWS * DM / 1024), 256>>>(x, xh, W1, W1Th, W2, W2Th, W3, W3Th);

    // q = x @ W1 -> qh (f16)
    gemm_h<false, true><<<dim3(DH / 128, ROWS / 128, 1), T, smem_bytes>>>(
        xh, W1Th, qh, nullptr, DM, DM, DM, DH, 0, 1.f, 0, 0, 0, 0);

    // kv = q @ W2 -> kvh (f16)
    gemm_h<false, true><<<dim3(2 * DH / 128, ROWS / 128, 1), T, smem_bytes>>>(
        qh, W2Th, kvh, nullptr, DH, DH, DH, 2 * DH, 0, 1.f, 0, 0, 0, 0);

    // vaT[b][p][l] = kvh[l][b][DH + p]
    transpose_h2h<<<dim3(DH / 32, SEQ / 32, NB), 256>>>(
        kvh + DH, vaTh, (long long)NB * 2 * DH, SEQ,
        (long long)(2 * DH), (long long)DH * SEQ);

    // scores[b] = scale * Q_b @ K_b^T -> attnh (f16, scaled)
    gemm_h<false, true><<<dim3(SEQ / 128, SEQ / 128, NB), T, smem_bytes>>>(
        qh, kvh, attnh, nullptr, DH, NB * DH, NB * 2 * DH, SEQ, 0, scale,
        (long long)DH, (long long)(2 * DH), (long long)SEQ * SEQ, 0);

    // softmax in place on fp16 rows
    softmax2048h<<<NB * SEQ, 256>>>(attnh);

    // cq[b] = attn_b @ vaT_b^T + qh_b -> cqh (f16)
    gemm_h<true, true><<<dim3(DH / 128, SEQ / 128, NB), T, smem_bytes>>>(
        attnh, vaTh, cqh, qh, SEQ, SEQ, SEQ, NB * DH, NB * DH, 1.f,
        (long long)SEQ * SEQ, (long long)DH * SEQ, (long long)DH, (long long)DH);

    // U = cq @ W3 -> Uh (f16)
    gemm_h<false, true><<<dim3(3 * DM / 128, ROWS / 128, 1), T, smem_bytes>>>(
        cqh, W3Th, Uh, nullptr, DH, DH, DH, 3 * DM, 0, 1.f, 0, 0, 0, 0);

    // elementwise highway recurrence over time
    sru_recur3<<<(NB * DM) / 256, 256, rec_smem>>>(Uh, x, v, bb, h);
}